// round 6
// baseline (speedup 1.0000x reference)
#include <cuda_runtime.h>
#include <math.h>

// ---------------- problem constants ----------------
#define TT 128   // seq len
#define BB 256   // batch
#define HH 512   // hidden
#define GG 2048  // 4*H gates
#define VV 128   // vocab
#define LL 128   // latent

typedef unsigned long long u64t;

// f32x2 packed helpers (FFMA2 in SASS)
__device__ __forceinline__ u64t pack2(float x, float y) {
    u64t r; asm("mov.b64 %0, {%1, %2};" : "=l"(r) : "f"(x), "f"(y)); return r;
}
__device__ __forceinline__ void fma2(u64t& d, u64t a, u64t b) {
    asm("fma.rn.f32x2 %0, %1, %2, %0;" : "+l"(d) : "l"(a), "l"(b));
}
__device__ __forceinline__ void add2(u64t& d, u64t a) {
    asm("add.rn.f32x2 %0, %0, %1;" : "+l"(d) : "l"(a));
}
__device__ __forceinline__ float2 unpack2(u64t v) {
    float2 r; asm("mov.b64 {%0, %1}, %2;" : "=f"(r.x), "=f"(r.y) : "l"(v)); return r;
}

// ---------------- device scratch ----------------
__device__ float g_seq [TT*BB*HH];
__device__ float g_seq1[TT*BB*2*HH];
__device__ float g_preF[TT*BB*GG];
__device__ float g_preB[TT*BB*GG];
__device__ float g_y0f [TT*BB*HH];
__device__ float g_y0b [TT*BB*HH];
__device__ float g_y1f [TT*BB*HH];
__device__ float g_y1b [TT*BB*HH];
__device__ float g_c0f [BB*HH];
__device__ float g_c0b [BB*HH];
__device__ float g_c1f [BB*HH];
__device__ float g_c1b [BB*HH];
__device__ float g_zeros[BB*HH];     // never written -> stays zero
__device__ float g_z   [BB*LL];
__device__ float g_dh0 [BB*HH];
__device__ float g_dh1 [BB*HH];
__device__ float g_dc0 [BB*HH];
__device__ float g_dc1 [BB*HH];
__device__ float g_part0[BB*GG];
__device__ float g_part1[BB*GG];
__device__ int   g_tok [BB];

// ---------------- software grid barrier ----------------
__device__ unsigned g_cnt;
__device__ volatile unsigned g_gen;

__device__ __forceinline__ void gbar(unsigned nb, unsigned& gen) {
    __threadfence();
    __syncthreads();
    if (threadIdx.x == 0) {
        if (atomicAdd(&g_cnt, 1u) == nb - 1) {
            g_cnt = 0;
            __threadfence();
            g_gen = gen + 1;
        } else {
            while (g_gen < gen + 1) __nanosleep(64);
        }
        __threadfence();
    }
    __syncthreads();
    gen++;
}

__device__ __forceinline__ float sigf(float v) { return 1.0f / (1.0f + expf(-v)); }

// ---------------- embedding gather ----------------
__global__ void embed_kernel(const int* __restrict__ x, const float* __restrict__ emb,
                             float* __restrict__ seq) {
    int total = TT*BB*HH;
    for (int i = blockIdx.x*blockDim.x + threadIdx.x; i < total; i += gridDim.x*blockDim.x) {
        int t = i / (BB*HH);
        int r = i % (BB*HH);
        int b = r / HH;
        int h = r % HH;
        seq[i] = emb[x[b*TT + t]*HH + h];
    }
}

// ---------------- concat ----------------
__global__ void concat_kernel(const float* __restrict__ yf, const float* __restrict__ yb,
                              float* __restrict__ seq1) {
    int total = TT*BB*2*HH;
    for (int i = blockIdx.x*blockDim.x + threadIdx.x; i < total; i += gridDim.x*blockDim.x) {
        int r = i / (2*HH);
        int j = i % (2*HH);
        seq1[i] = (j < HH) ? yf[r*HH + j] : yb[r*HH + j - HH];
    }
}

// ================= SGEMM (f32x2): C[M,N] = A[M,K] @ W[N,K]^T + bias[N] =================
#define PBM 128
#define PBN 128
#define PBK 16
#define PA_LD 132
#define PW_LD 132

__global__ __launch_bounds__(256) void sgemm_bias_f(const float* __restrict__ A,
                                                    const float* __restrict__ W,
                                                    const float* __restrict__ bias,
                                                    float* __restrict__ C,
                                                    int M, int N, int K) {
    __shared__ __align__(16) float As[PBK*PA_LD];
    __shared__ __align__(16) float Ws[PBK*PW_LD];
    const int bm = blockIdx.y * PBM;
    const int bn = blockIdx.x * PBN;
    const int tid = threadIdx.x;
    const int tx = tid % 16;
    const int ty = tid / 16;
    const int am = tid >> 1;
    const int ak = (tid & 1) * 8;

    const float* ap = A + (size_t)(bm + am)*K + ak;
    const float* wp = W + (size_t)(bn + am)*K + ak;

    float4 ra0 = *(const float4*)(ap);
    float4 ra1 = *(const float4*)(ap + 4);
    float4 rw0 = *(const float4*)(wp);
    float4 rw1 = *(const float4*)(wp + 4);

    u64t acc2[4][8];
    #pragma unroll
    for (int p = 0; p < 4; p++)
        #pragma unroll
        for (int j = 0; j < 8; j++) acc2[p][j] = 0ull;

    for (int k0 = 0; k0 < K; k0 += PBK) {
        As[(ak+0)*PA_LD + am] = ra0.x; As[(ak+1)*PA_LD + am] = ra0.y;
        As[(ak+2)*PA_LD + am] = ra0.z; As[(ak+3)*PA_LD + am] = ra0.w;
        As[(ak+4)*PA_LD + am] = ra1.x; As[(ak+5)*PA_LD + am] = ra1.y;
        As[(ak+6)*PA_LD + am] = ra1.z; As[(ak+7)*PA_LD + am] = ra1.w;
        Ws[(ak+0)*PW_LD + am] = rw0.x; Ws[(ak+1)*PW_LD + am] = rw0.y;
        Ws[(ak+2)*PW_LD + am] = rw0.z; Ws[(ak+3)*PW_LD + am] = rw0.w;
        Ws[(ak+4)*PW_LD + am] = rw1.x; Ws[(ak+5)*PW_LD + am] = rw1.y;
        Ws[(ak+6)*PW_LD + am] = rw1.z; Ws[(ak+7)*PW_LD + am] = rw1.w;
        __syncthreads();

        if (k0 + PBK < K) {
            ra0 = *(const float4*)(ap + k0 + PBK);
            ra1 = *(const float4*)(ap + k0 + PBK + 4);
            rw0 = *(const float4*)(wp + k0 + PBK);
            rw1 = *(const float4*)(wp + k0 + PBK + 4);
        }

        #pragma unroll
        for (int k = 0; k < PBK; k++) {
            ulonglong2 A0 = *(const ulonglong2*)&As[k*PA_LD + ty*8];
            ulonglong2 A1 = *(const ulonglong2*)&As[k*PA_LD + ty*8 + 4];
            u64t apair[4] = {A0.x, A0.y, A1.x, A1.y};
            float w[8];
            *(float4*)&w[0] = *(const float4*)&Ws[k*PW_LD + tx*8];
            *(float4*)&w[4] = *(const float4*)&Ws[k*PW_LD + tx*8 + 4];
            #pragma unroll
            for (int j = 0; j < 8; j++) {
                u64t w2 = pack2(w[j], w[j]);
                #pragma unroll
                for (int p = 0; p < 4; p++) fma2(acc2[p][j], apair[p], w2);
            }
        }
        __syncthreads();
    }

    float bb[8];
    *(float4*)&bb[0] = *(const float4*)(bias + bn + tx*8);
    *(float4*)&bb[4] = *(const float4*)(bias + bn + tx*8 + 4);
    #pragma unroll
    for (int p = 0; p < 4; p++) {
        float2 v[8];
        #pragma unroll
        for (int j = 0; j < 8; j++) v[j] = unpack2(acc2[p][j]);
        #pragma unroll
        for (int sub = 0; sub < 2; sub++) {
            size_t row = (size_t)(bm + ty*8 + 2*p + sub)*N + bn + tx*8;
            float o[8];
            #pragma unroll
            for (int j = 0; j < 8; j++) o[j] = (sub ? v[j].y : v[j].x) + bb[j];
            *(float4*)&C[row]     = *(float4*)&o[0];
            *(float4*)&C[row + 4] = *(float4*)&o[4];
        }
    }
}

// ====== 4-gate GEMM core, split-K, 512 threads: 64 batch x 32 hcols x 4 gates =========
// W staged as [k][col][gate] 16B vectors -> one LDS.128 per k gets all 4 gate scalars.
#define RBM 64
#define RBN 32
#define RBK 32
#define KSPLIT 256
#define HS_LD 68                      // RBM+4
#define HS_FLOATS (RBK*HS_LD)         // 2176
#define WS4_FLOATS (RBK*RBN*4)        // 4096
#define SMEM_FLOATS (2*HS_FLOATS + 2*WS4_FLOATS)   // 12544 floats = 50176 B

template<bool GATHER, bool CG>
__device__ __forceinline__ void gate_gemm_ks(const float* __restrict__ Abase,
                                             const int* __restrict__ tok,
                                             const float* __restrict__ emb,
                                             const float* __restrict__ W,
                                             int bm, int bn, int kbeg,
                                             float* __restrict__ Hs,
                                             float* __restrict__ Ws4,
                                             u64t acc2[4][4]) {
    const int lt = threadIdx.x & 255;
    const int tx = lt & 31;        // col
    const int ty = lt >> 5;        // row-octet
    const int hm = lt >> 2;        // 0..63
    const int hk = (lt & 3) * 8;   // 0,8,16,24
    const int wr = lt >> 1;        // 0..127 = gate*32 + col
    const int wk = (lt & 1) * 16;  // 0 or 16
    const int wg = wr >> 5;
    const int wn = wr & 31;

    const float* hp;
    if (GATHER) {
        int tk = __ldcg(&tok[bm + hm]);
        hp = emb + (size_t)tk*HH + kbeg + hk;
    } else {
        hp = Abase + (size_t)(bm + hm)*HH + kbeg + hk;
    }
    const float* wp = W + (size_t)(wg*HH + bn + wn)*HH + kbeg + wk;

    float4 ha0, ha1;
    if (CG && !GATHER) { ha0 = __ldcg((const float4*)hp); ha1 = __ldcg((const float4*)(hp + 4)); }
    else               { ha0 = *(const float4*)hp;        ha1 = *(const float4*)(hp + 4); }
    float4 wa0 = *(const float4*)(wp);
    float4 wa1 = *(const float4*)(wp + 4);
    float4 wa2 = *(const float4*)(wp + 8);
    float4 wa3 = *(const float4*)(wp + 12);

    for (int kt = 0; kt < KSPLIT; kt += RBK) {
        Hs[(hk+0)*HS_LD + hm] = ha0.x; Hs[(hk+1)*HS_LD + hm] = ha0.y;
        Hs[(hk+2)*HS_LD + hm] = ha0.z; Hs[(hk+3)*HS_LD + hm] = ha0.w;
        Hs[(hk+4)*HS_LD + hm] = ha1.x; Hs[(hk+5)*HS_LD + hm] = ha1.y;
        Hs[(hk+6)*HS_LD + hm] = ha1.z; Hs[(hk+7)*HS_LD + hm] = ha1.w;
        {
            float w[16] = {wa0.x,wa0.y,wa0.z,wa0.w, wa1.x,wa1.y,wa1.z,wa1.w,
                           wa2.x,wa2.y,wa2.z,wa2.w, wa3.x,wa3.y,wa3.z,wa3.w};
            #pragma unroll
            for (int j = 0; j < 16; j++)
                Ws4[((wk + j)*RBN + wn)*4 + wg] = w[j];
        }
        __syncthreads();

        if (kt + RBK < KSPLIT) {
            if (CG && !GATHER) {
                ha0 = __ldcg((const float4*)(hp + kt + RBK));
                ha1 = __ldcg((const float4*)(hp + kt + RBK + 4));
            } else {
                ha0 = *(const float4*)(hp + kt + RBK);
                ha1 = *(const float4*)(hp + kt + RBK + 4);
            }
            wa0 = *(const float4*)(wp + kt + RBK);
            wa1 = *(const float4*)(wp + kt + RBK + 4);
            wa2 = *(const float4*)(wp + kt + RBK + 8);
            wa3 = *(const float4*)(wp + kt + RBK + 12);
        }

        #pragma unroll 8
        for (int k = 0; k < RBK; k++) {
            ulonglong2 A0 = *(const ulonglong2*)&Hs[k*HS_LD + ty*8];      // broadcast
            ulonglong2 A1 = *(const ulonglong2*)&Hs[k*HS_LD + ty*8 + 4];  // broadcast
            float4 wv = *(const float4*)&Ws4[(k*RBN + tx)*4];              // 4 gates
            u64t wi = pack2(wv.x, wv.x);
            u64t wf = pack2(wv.y, wv.y);
            u64t wg2 = pack2(wv.z, wv.z);
            u64t wo = pack2(wv.w, wv.w);
            fma2(acc2[0][0], A0.x, wi);  fma2(acc2[0][1], A0.y, wi);
            fma2(acc2[0][2], A1.x, wi);  fma2(acc2[0][3], A1.y, wi);
            fma2(acc2[1][0], A0.x, wf);  fma2(acc2[1][1], A0.y, wf);
            fma2(acc2[1][2], A1.x, wf);  fma2(acc2[1][3], A1.y, wf);
            fma2(acc2[2][0], A0.x, wg2); fma2(acc2[2][1], A0.y, wg2);
            fma2(acc2[2][2], A1.x, wg2); fma2(acc2[2][3], A1.y, wg2);
            fma2(acc2[3][0], A0.x, wo);  fma2(acc2[3][1], A0.y, wo);
            fma2(acc2[3][2], A1.x, wo);  fma2(acc2[3][3], A1.y, wo);
        }
        __syncthreads();
    }
}

// Merge half-1 partials into half-0 accumulators via smem.
__device__ __forceinline__ void ksplit_merge(float* __restrict__ smemAll,
                                             u64t acc2[4][4], int half) {
    u64t* red = reinterpret_cast<u64t*>(smemAll);
    const int lt = threadIdx.x & 255;
    if (half == 1) {
        #pragma unroll
        for (int g = 0; g < 4; g++)
            #pragma unroll
            for (int p = 0; p < 4; p++)
                red[lt*16 + g*4 + p] = acc2[g][p];
    }
    __syncthreads();
    if (half == 0) {
        #pragma unroll
        for (int g = 0; g < 4; g++)
            #pragma unroll
            for (int p = 0; p < 4; p++)
                add2(acc2[g][p], red[lt*16 + g*4 + p]);
    }
}

// LSTM elementwise epilogue (half-0 threads: 8 rows x 1 col each)
template<bool CG>
__device__ __forceinline__ void lstm_epilogue(u64t acc2[4][4],
                                              const float* __restrict__ pre,
                                              const float* __restrict__ cin,
                                              float* __restrict__ cout,
                                              float* __restrict__ hout,
                                              int bm, int bn) {
    const int lt = threadIdx.x & 255;
    const int tx = lt & 31;
    const int ty = lt >> 5;
    const int n = bn + tx;
    #pragma unroll
    for (int p = 0; p < 4; p++) {
        float2 vi = unpack2(acc2[0][p]);
        float2 vf = unpack2(acc2[1][p]);
        float2 vg = unpack2(acc2[2][p]);
        float2 vo = unpack2(acc2[3][p]);
        #pragma unroll
        for (int sub = 0; sub < 2; sub++) {
            int b = bm + ty*8 + 2*p + sub;
            const float* pb = pre + (size_t)b*GG;
            float pi, pf, pg, po, cv;
            if (CG) {
                pi = __ldcg(pb + 0*HH + n); pf = __ldcg(pb + 1*HH + n);
                pg = __ldcg(pb + 2*HH + n); po = __ldcg(pb + 3*HH + n);
                cv = __ldcg(cin + (size_t)b*HH + n);
            } else {
                pi = pb[0*HH + n]; pf = pb[1*HH + n];
                pg = pb[2*HH + n]; po = pb[3*HH + n];
                cv = cin[(size_t)b*HH + n];
            }
            float gi = pi + (sub ? vi.y : vi.x);
            float gf = pf + (sub ? vf.y : vf.x);
            float gg = pg + (sub ? vg.y : vg.x);
            float go = po + (sub ? vo.y : vo.x);
            float cn = sigf(gf)*cv + sigf(gi)*tanhf(gg);
            cout[(size_t)b*HH + n] = cn;
            hout[(size_t)b*HH + n] = sigf(go)*tanhf(cn);
        }
    }
}

// partial writer: outp[b, g*H+n] = acc + bias
__device__ __forceinline__ void part_store(u64t acc2[4][4],
                                           const float* __restrict__ bias,
                                           float* __restrict__ outp,
                                           int bm, int bn) {
    const int lt = threadIdx.x & 255;
    const int tx = lt & 31;
    const int ty = lt >> 5;
    const int n = bn + tx;
    #pragma unroll
    for (int g = 0; g < 4; g++) {
        float bv = bias[g*HH + n];
        #pragma unroll
        for (int p = 0; p < 4; p++) {
            float2 v = unpack2(acc2[g][p]);
            int b0 = bm + ty*8 + 2*p;
            outp[(size_t)(b0+0)*GG + g*HH + n] = v.x + bv;
            outp[(size_t)(b0+1)*GG + g*HH + n] = v.y + bv;
        }
    }
}

#define ZERO_ACC(acc2) { _Pragma("unroll") for (int g_ = 0; g_ < 4; g_++) { \
    _Pragma("unroll") for (int p_ = 0; p_ < 4; p_++) acc2[g_][p_] = 0ull; } }

// =============== persistent encoder layer: 128 steps, both dirs, one launch ============
__global__ __launch_bounds__(512, 1) void enc_layer_persist(
    const float* __restrict__ preF, const float* __restrict__ preB,
    float* __restrict__ yF, float* __restrict__ yB,
    float* __restrict__ cF, float* __restrict__ cB,
    const float* __restrict__ WhhF, const float* __restrict__ WhhB,
    const float* __restrict__ zeros) {
    __shared__ __align__(16) float S[SMEM_FLOATS];
    const int half = threadIdx.x >> 8;
    float* Hs  = S + half*HS_FLOATS;
    float* Ws4 = S + 2*HS_FLOATS + half*WS4_FLOATS;
    const int dir = blockIdx.z;
    const int bm = blockIdx.y * RBM;
    const int bn = blockIdx.x * RBN;
    const float* Whh = dir ? WhhB : WhhF;
    unsigned gen = 0;
    if (threadIdx.x == 0) gen = g_gen;

    for (int s = 0; s < TT; s++) {
        const float* pre; const float* hin; const float* cin;
        float* cout; float* hout;
        if (dir == 0) {
            int tf = s;
            pre = preF + (size_t)tf*BB*GG;
            hin = s ? yF + (size_t)(tf-1)*BB*HH : zeros;
            cin = s ? cF : zeros;
            cout = cF;
            hout = yF + (size_t)tf*BB*HH;
        } else {
            int tb = TT-1-s;
            pre = preB + (size_t)tb*BB*GG;
            hin = s ? yB + (size_t)(tb+1)*BB*HH : zeros;
            cin = s ? cB : zeros;
            cout = cB;
            hout = yB + (size_t)tb*BB*HH;
        }
        u64t acc2[4][4];
        ZERO_ACC(acc2);
        gate_gemm_ks<false,false>(hin, nullptr, nullptr, Whh, bm, bn, half*KSPLIT, Hs, Ws4, acc2);
        ksplit_merge(S, acc2, half);
        if (half == 0)
            lstm_epilogue<false>(acc2, pre, cin, cout, hout, bm, bn);
        gbar(128, gen);
    }
}

// =============== persistent decoder: 128 steps x (cell0||part1, cell1||part0, argmax) ==
__global__ __launch_bounds__(512, 1) void dec_persist(
    const float* __restrict__ emb,
    const float* __restrict__ Wih0, const float* __restrict__ Whh0, const float* __restrict__ b0,
    const float* __restrict__ Wih1, const float* __restrict__ Whh1, const float* __restrict__ b1,
    const float* __restrict__ Wout, const float* __restrict__ bout,
    float* __restrict__ dh0, float* __restrict__ dh1,
    float* __restrict__ dc0, float* __restrict__ dc1,
    float* __restrict__ part0, float* __restrict__ part1,
    int* __restrict__ tok, float* __restrict__ recon) {
    __shared__ __align__(16) float S[SMEM_FLOATS];
    const int half = threadIdx.x >> 8;
    float* Hs  = S + half*HS_FLOATS;
    float* Ws4 = S + 2*HS_FLOATS + half*WS4_FLOATS;
    const int role = blockIdx.z;                      // 0 = cells, 1 = partials+argmax
    const int bm = blockIdx.y * RBM;
    const int bn = blockIdx.x * RBN;
    const int bid = blockIdx.y * 16 + blockIdx.x;     // 0..63 within role
    const int tid = threadIdx.x;
    unsigned gen = 0;
    if (tid == 0) gen = g_gen;

    for (int t = 0; t < TT; t++) {
        u64t acc2[4][4];
        // ---- Phase A: cell0 (emb[tok]@Wih0 + part0) || part1 = dh1@Whh1 + b1
        ZERO_ACC(acc2);
        if (role == 0) {
            gate_gemm_ks<true,true>(nullptr, tok, emb, Wih0, bm, bn, half*KSPLIT, Hs, Ws4, acc2);
            ksplit_merge(S, acc2, half);
            if (half == 0) lstm_epilogue<true>(acc2, part0, dc0, dc0, dh0, bm, bn);
        } else {
            gate_gemm_ks<false,true>(dh1, nullptr, nullptr, Whh1, bm, bn, half*KSPLIT, Hs, Ws4, acc2);
            ksplit_merge(S, acc2, half);
            if (half == 0) part_store(acc2, b1, part1, bm, bn);
        }
        gbar(128, gen);

        // ---- Phase B: cell1 (dh0@Wih1 + part1) || part0 = dh0@Whh0 + b0 (for t+1)
        ZERO_ACC(acc2);
        if (role == 0) {
            gate_gemm_ks<false,true>(dh0, nullptr, nullptr, Wih1, bm, bn, half*KSPLIT, Hs, Ws4, acc2);
            ksplit_merge(S, acc2, half);
            if (half == 0) lstm_epilogue<true>(acc2, part1, dc1, dc1, dh1, bm, bn);
        } else {
            gate_gemm_ks<false,true>(dh0, nullptr, nullptr, Whh0, bm, bn, half*KSPLIT, Hs, Ws4, acc2);
            ksplit_merge(S, acc2, half);
            if (half == 0) part_store(acc2, b0, part0, bm, bn);
        }
        gbar(128, gen);

        // ---- Phase C: logits + argmax (role==1 blocks, 4 batch rows each)
        if (role == 1) {
            float* sh = S;                         // 4 x 512
            float* sv = S + 4*HH;                  // 4 x 128
            int*   si = (int*)(S + 4*HH + 4*VV);   // 4 x 128
            int b0r = bid * 4;
            for (int i = tid; i < 4*HH/4; i += 512)
                ((float4*)sh)[i] = __ldcg(((const float4*)(dh1 + (size_t)b0r*HH)) + i);
            __syncthreads();
            int v = tid & 127;
            int rw = tid >> 7;
            const float4* w4 = (const float4*)(Wout + (size_t)v*HH);
            const float* shr = sh + rw*HH;
            float acc = bout[v];
            #pragma unroll 4
            for (int k = 0; k < HH/4; k++) {
                float4 wv = w4[k];
                float4 s4 = *(const float4*)&shr[k*4];
                acc += s4.x*wv.x + s4.y*wv.y + s4.z*wv.z + s4.w*wv.w;
            }
            recon[(size_t)(b0r+rw)*TT*VV + (size_t)t*VV + v] = acc;
            sv[rw*VV + v] = acc;
            si[rw*VV + v] = v;
            __syncthreads();
            for (int s2 = 64; s2 > 0; s2 >>= 1) {
                if (v < s2) {
                    float ov = sv[rw*VV + v + s2]; int oi = si[rw*VV + v + s2];
                    if (ov > sv[rw*VV + v] || (ov == sv[rw*VV + v] && oi < si[rw*VV + v])) {
                        sv[rw*VV + v] = ov; si[rw*VV + v] = oi;
                    }
                }
                __syncthreads();
            }
            if (tid < 4) tok[b0r + tid] = si[tid*VV];
        }
        gbar(128, gen);
    }
}

// ---------------- mu/logvar heads ----------------
__global__ __launch_bounds__(256) void head_kernel(const float* __restrict__ hf,
                                                   const float* __restrict__ hb,
                                                   const float* __restrict__ Wmu,
                                                   const float* __restrict__ bmu,
                                                   const float* __restrict__ Wlv,
                                                   const float* __restrict__ blv,
                                                   float* __restrict__ out_mu,
                                                   float* __restrict__ out_lv,
                                                   float* __restrict__ zbuf) {
    int b = blockIdx.x;
    int tid = threadIdx.x;
    __shared__ float sh[2*HH];
    for (int i = tid; i < HH; i += 256) {
        sh[i]      = hf[b*HH + i];
        sh[HH + i] = hb[b*HH + i];
    }
    __syncthreads();
    const float* W;
    float acc;
    int l;
    if (tid < LL) { l = tid;      W = Wmu + (size_t)l*2*HH; acc = bmu[l]; }
    else          { l = tid - LL; W = Wlv + (size_t)l*2*HH; acc = blv[l]; }
    #pragma unroll 8
    for (int k = 0; k < 2*HH; k++) acc += sh[k]*W[k];
    if (tid < LL) { out_mu[b*LL + l] = acc; zbuf[b*LL + l] = acc; }
    else          { out_lv[b*LL + l] = acc; }
}

// ---------------- decoder init ----------------
__global__ __launch_bounds__(512) void dec_init_kernel(const float* __restrict__ z,
                                                       const float* __restrict__ W,
                                                       const float* __restrict__ bias,
                                                       float* __restrict__ h0,
                                                       float* __restrict__ h1,
                                                       float* __restrict__ c0,
                                                       float* __restrict__ c1,
                                                       int* __restrict__ tok) {
    int b = blockIdx.x;
    int tid = threadIdx.x;
    __shared__ float sz[LL];
    if (tid < LL) sz[tid] = z[b*LL + tid];
    __syncthreads();
    float acc = bias[tid];
    const float* w = W + (size_t)tid*LL;
    #pragma unroll 8
    for (int k = 0; k < LL; k++) acc += sz[k]*w[k];
    h0[b*HH + tid] = acc;
    h1[b*HH + tid] = acc;
    c0[b*HH + tid] = 0.0f;
    c1[b*HH + tid] = 0.0f;
    if (tid == 0) tok[b] = 1;
}

// =================================== host launcher ====================================
extern "C" void kernel_launch(void* const* d_in, const int* in_sizes, int n_in,
                              void* d_out, int out_size) {
    const int*   x           = (const int*)  d_in[0];
    const float* emb         = (const float*)d_in[1];
    const float* enc_wih_l0  = (const float*)d_in[2];
    const float* enc_whh_l0  = (const float*)d_in[3];
    const float* enc_b_l0    = (const float*)d_in[4];
    const float* enc_wih_l1  = (const float*)d_in[5];
    const float* enc_whh_l1  = (const float*)d_in[6];
    const float* enc_b_l1    = (const float*)d_in[7];
    const float* fc_mu_w     = (const float*)d_in[8];
    const float* fc_mu_b     = (const float*)d_in[9];
    const float* fc_lv_w     = (const float*)d_in[10];
    const float* fc_lv_b     = (const float*)d_in[11];
    const float* dec_in_w    = (const float*)d_in[12];
    const float* dec_in_b    = (const float*)d_in[13];
    const float* dec_wih     = (const float*)d_in[14];
    const float* dec_whh     = (const float*)d_in[15];
    const float* dec_b       = (const float*)d_in[16];
    const float* dec_out_w   = (const float*)d_in[17];
    const float* dec_out_b   = (const float*)d_in[18];

    float* out       = (float*)d_out;
    float* out_recon = out;
    float* out_mu    = out + (size_t)BB*TT*VV;
    float* out_lv    = out_mu + (size_t)BB*LL;

    float *seq, *seq1, *preF, *preB, *y0f, *y0b, *y1f, *y1b;
    float *c0f, *c0b, *c1f, *c1b, *zeros, *zbuf, *dh0, *dh1, *dc0, *dc1;
    float *part0, *part1;
    int* tokp;
    cudaGetSymbolAddress((void**)&seq,   g_seq);
    cudaGetSymbolAddress((void**)&seq1,  g_seq1);
    cudaGetSymbolAddress((void**)&preF,  g_preF);
    cudaGetSymbolAddress((void**)&preB,  g_preB);
    cudaGetSymbolAddress((void**)&y0f,   g_y0f);
    cudaGetSymbolAddress((void**)&y0b,   g_y0b);
    cudaGetSymbolAddress((void**)&y1f,   g_y1f);
    cudaGetSymbolAddress((void**)&y1b,   g_y1b);
    cudaGetSymbolAddress((void**)&c0f,   g_c0f);
    cudaGetSymbolAddress((void**)&c0b,   g_c0b);
    cudaGetSymbolAddress((void**)&c1f,   g_c1f);
    cudaGetSymbolAddress((void**)&c1b,   g_c1b);
    cudaGetSymbolAddress((void**)&zeros, g_zeros);
    cudaGetSymbolAddress((void**)&zbuf,  g_z);
    cudaGetSymbolAddress((void**)&dh0,   g_dh0);
    cudaGetSymbolAddress((void**)&dh1,   g_dh1);
    cudaGetSymbolAddress((void**)&dc0,   g_dc0);
    cudaGetSymbolAddress((void**)&dc1,   g_dc1);
    cudaGetSymbolAddress((void**)&part0, g_part0);
    cudaGetSymbolAddress((void**)&part1, g_part1);
    cudaGetSymbolAddress((void**)&tokp,  g_tok);

    // 1) embedding
    embed_kernel<<<2048, 256>>>(x, emb, seq);

    // 2) encoder layer 0: pre-GEMMs + persistent recurrence
    dim3 preGrd(GG/PBN, (TT*BB)/PBM);
    sgemm_bias_f<<<preGrd, 256>>>(seq, enc_wih_l0,                 enc_b_l0,      preF, TT*BB, GG, HH);
    sgemm_bias_f<<<preGrd, 256>>>(seq, enc_wih_l0 + (size_t)GG*HH, enc_b_l0 + GG, preB, TT*BB, GG, HH);
    dim3 perGrd(HH/RBN, BB/RBM, 2);   // (16,4,2) = 128 blocks
    enc_layer_persist<<<perGrd, 512>>>(preF, preB, y0f, y0b, c0f, c0b,
                                       enc_whh_l0, enc_whh_l0 + (size_t)GG*HH, zeros);

    // 3) encoder layer 1
    concat_kernel<<<2048, 256>>>(y0f, y0b, seq1);
    sgemm_bias_f<<<preGrd, 256>>>(seq1, enc_wih_l1,                   enc_b_l1,      preF, TT*BB, GG, 2*HH);
    sgemm_bias_f<<<preGrd, 256>>>(seq1, enc_wih_l1 + (size_t)GG*2*HH, enc_b_l1 + GG, preB, TT*BB, GG, 2*HH);
    enc_layer_persist<<<perGrd, 512>>>(preF, preB, y1f, y1b, c1f, c1b,
                                       enc_whh_l1, enc_whh_l1 + (size_t)GG*HH, zeros);

    // 4) heads
    head_kernel<<<BB, 256>>>(y1f + (size_t)(TT-1)*BB*HH, y1b,
                             fc_mu_w, fc_mu_b, fc_lv_w, fc_lv_b,
                             out_mu, out_lv, zbuf);

    // 5) decoder init + initial part0 = dh0@Whh0 + b0
    dec_init_kernel<<<BB, 512>>>(zbuf, dec_in_w, dec_in_b, dh0, dh1, dc0, dc1, tokp);
    sgemm_bias_f<<<dim3(GG/PBN, BB/PBM), 256>>>(dh0, dec_whh, dec_b, part0, BB, GG, HH);

    // 6) persistent autoregressive decoder (single launch, 128 steps)
    dec_persist<<<perGrd, 512>>>(emb,
                                 dec_wih, dec_whh, dec_b,
                                 dec_wih + (size_t)GG*HH, dec_whh + (size_t)GG*HH, dec_b + GG,
                                 dec_out_w, dec_out_b,
                                 dh0, dh1, dc0, dc1, part0, part1, tokp, out_recon);
}

// round 7
// speedup vs baseline: 1.1719x; 1.1719x over previous
#include <cuda_runtime.h>
#include <math.h>

// ---------------- problem constants ----------------
#define TT 128   // seq len
#define BB 256   // batch
#define HH 512   // hidden
#define GG 2048  // 4*H gates
#define VV 128   // vocab
#define LL 128   // latent

typedef unsigned long long u64t;

// f32x2 packed helpers (FFMA2 in SASS)
__device__ __forceinline__ u64t pack2(float x, float y) {
    u64t r; asm("mov.b64 %0, {%1, %2};" : "=l"(r) : "f"(x), "f"(y)); return r;
}
__device__ __forceinline__ void fma2(u64t& d, u64t a, u64t b) {
    asm("fma.rn.f32x2 %0, %1, %2, %0;" : "+l"(d) : "l"(a), "l"(b));
}
__device__ __forceinline__ void add2(u64t& d, u64t a) {
    asm("add.rn.f32x2 %0, %0, %1;" : "+l"(d) : "l"(a));
}
__device__ __forceinline__ float2 unpack2(u64t v) {
    float2 r; asm("mov.b64 {%0, %1}, %2;" : "=f"(r.x), "=f"(r.y) : "l"(v)); return r;
}

// ---------------- device scratch ----------------
__device__ float g_seq [TT*BB*HH];
__device__ float g_seq1[TT*BB*2*HH];
__device__ float g_preF[TT*BB*GG];
__device__ float g_preB[TT*BB*GG];
__device__ float g_y0f [TT*BB*HH];
__device__ float g_y0b [TT*BB*HH];
__device__ float g_y1f [TT*BB*HH];
__device__ float g_y1b [TT*BB*HH];
__device__ float g_c0f [BB*HH];
__device__ float g_c0b [BB*HH];
__device__ float g_c1f [BB*HH];
__device__ float g_c1b [BB*HH];
__device__ float g_zeros[BB*HH];     // never written -> stays zero
__device__ float g_z   [BB*LL];
__device__ float g_dh0 [BB*HH];
__device__ float g_dh1 [BB*HH];
__device__ float g_dc0 [BB*HH];
__device__ float g_dc1 [BB*HH];
__device__ float g_part0[BB*GG];     // dh0@Whh0            (bias folded into Ptab)
__device__ float g_part1[BB*GG];     // dh1@Whh1 + b1
__device__ float g_ptab [VV*GG];     // emb@Wih0^T + b0, all 128 tokens

__device__ __forceinline__ float sigf(float v) { return 1.0f / (1.0f + expf(-v)); }

// ---------------- embedding gather ----------------
__global__ void embed_kernel(const int* __restrict__ x, const float* __restrict__ emb,
                             float* __restrict__ seq) {
    int total = TT*BB*HH;
    for (int i = blockIdx.x*blockDim.x + threadIdx.x; i < total; i += gridDim.x*blockDim.x) {
        int t = i / (BB*HH);
        int r = i % (BB*HH);
        int b = r / HH;
        int h = r % HH;
        seq[i] = emb[x[b*TT + t]*HH + h];
    }
}

// ---------------- concat ----------------
__global__ void concat_kernel(const float* __restrict__ yf, const float* __restrict__ yb,
                              float* __restrict__ seq1) {
    int total = TT*BB*2*HH;
    for (int i = blockIdx.x*blockDim.x + threadIdx.x; i < total; i += gridDim.x*blockDim.x) {
        int r = i / (2*HH);
        int j = i % (2*HH);
        seq1[i] = (j < HH) ? yf[r*HH + j] : yb[r*HH + j - HH];
    }
}

// ====== SGEMM (f32x2, ping-pong smem): C[M,N] = A[M,K] @ W[N,K]^T + bias[N] ============
#define PBM 128
#define PBN 128
#define PBK 16
#define PA_LD 132
#define PW_LD 132

__global__ __launch_bounds__(256) void sgemm_bias_f(const float* __restrict__ A,
                                                    const float* __restrict__ W,
                                                    const float* __restrict__ bias,
                                                    float* __restrict__ C,
                                                    int M, int N, int K) {
    __shared__ __align__(16) float As[2][PBK*PA_LD];
    __shared__ __align__(16) float Ws[2][PBK*PW_LD];
    const int bm = blockIdx.y * PBM;
    const int bn = blockIdx.x * PBN;
    const int tid = threadIdx.x;
    const int tx = tid % 16;
    const int ty = tid / 16;
    const int am = tid >> 1;
    const int ak = (tid & 1) * 8;

    const float* ap = A + (size_t)(bm + am)*K + ak;
    const float* wp = W + (size_t)(bn + am)*K + ak;

    float4 ra0 = *(const float4*)(ap);
    float4 ra1 = *(const float4*)(ap + 4);
    float4 rw0 = *(const float4*)(wp);
    float4 rw1 = *(const float4*)(wp + 4);

    u64t acc2[4][8];
    #pragma unroll
    for (int p = 0; p < 4; p++)
        #pragma unroll
        for (int j = 0; j < 8; j++) acc2[p][j] = 0ull;

    const int NS = K / PBK;
    // store stage 0
    {
        float* Ab = As[0]; float* Wb = Ws[0];
        Ab[(ak+0)*PA_LD + am] = ra0.x; Ab[(ak+1)*PA_LD + am] = ra0.y;
        Ab[(ak+2)*PA_LD + am] = ra0.z; Ab[(ak+3)*PA_LD + am] = ra0.w;
        Ab[(ak+4)*PA_LD + am] = ra1.x; Ab[(ak+5)*PA_LD + am] = ra1.y;
        Ab[(ak+6)*PA_LD + am] = ra1.z; Ab[(ak+7)*PA_LD + am] = ra1.w;
        Wb[(ak+0)*PW_LD + am] = rw0.x; Wb[(ak+1)*PW_LD + am] = rw0.y;
        Wb[(ak+2)*PW_LD + am] = rw0.z; Wb[(ak+3)*PW_LD + am] = rw0.w;
        Wb[(ak+4)*PW_LD + am] = rw1.x; Wb[(ak+5)*PW_LD + am] = rw1.y;
        Wb[(ak+6)*PW_LD + am] = rw1.z; Wb[(ak+7)*PW_LD + am] = rw1.w;
    }
    __syncthreads();
    ra0 = *(const float4*)(ap + PBK);     ra1 = *(const float4*)(ap + PBK + 4);
    rw0 = *(const float4*)(wp + PBK);     rw1 = *(const float4*)(wp + PBK + 4);

    #pragma unroll 2
    for (int s = 0; s < NS; s++) {
        const float* Ab = As[s & 1];
        const float* Wb = Ws[s & 1];
        #pragma unroll
        for (int k = 0; k < PBK; k++) {
            ulonglong2 A0 = *(const ulonglong2*)&Ab[k*PA_LD + ty*8];
            ulonglong2 A1 = *(const ulonglong2*)&Ab[k*PA_LD + ty*8 + 4];
            u64t apair[4] = {A0.x, A0.y, A1.x, A1.y};
            float w[8];
            *(float4*)&w[0] = *(const float4*)&Wb[k*PW_LD + tx*8];
            *(float4*)&w[4] = *(const float4*)&Wb[k*PW_LD + tx*8 + 4];
            #pragma unroll
            for (int j = 0; j < 8; j++) {
                u64t w2 = pack2(w[j], w[j]);
                #pragma unroll
                for (int p = 0; p < 4; p++) fma2(acc2[p][j], apair[p], w2);
            }
        }
        if (s < NS - 1) {
            float* An = As[(s+1) & 1]; float* Wn = Ws[(s+1) & 1];
            An[(ak+0)*PA_LD + am] = ra0.x; An[(ak+1)*PA_LD + am] = ra0.y;
            An[(ak+2)*PA_LD + am] = ra0.z; An[(ak+3)*PA_LD + am] = ra0.w;
            An[(ak+4)*PA_LD + am] = ra1.x; An[(ak+5)*PA_LD + am] = ra1.y;
            An[(ak+6)*PA_LD + am] = ra1.z; An[(ak+7)*PA_LD + am] = ra1.w;
            Wn[(ak+0)*PW_LD + am] = rw0.x; Wn[(ak+1)*PW_LD + am] = rw0.y;
            Wn[(ak+2)*PW_LD + am] = rw0.z; Wn[(ak+3)*PW_LD + am] = rw0.w;
            Wn[(ak+4)*PW_LD + am] = rw1.x; Wn[(ak+5)*PW_LD + am] = rw1.y;
            Wn[(ak+6)*PW_LD + am] = rw1.z; Wn[(ak+7)*PW_LD + am] = rw1.w;
            __syncthreads();
            if (s < NS - 2) {
                ra0 = *(const float4*)(ap + (s+2)*PBK);
                ra1 = *(const float4*)(ap + (s+2)*PBK + 4);
                rw0 = *(const float4*)(wp + (s+2)*PBK);
                rw1 = *(const float4*)(wp + (s+2)*PBK + 4);
            }
        }
    }

    float bb[8];
    *(float4*)&bb[0] = *(const float4*)(bias + bn + tx*8);
    *(float4*)&bb[4] = *(const float4*)(bias + bn + tx*8 + 4);
    #pragma unroll
    for (int p = 0; p < 4; p++) {
        float2 v[8];
        #pragma unroll
        for (int j = 0; j < 8; j++) v[j] = unpack2(acc2[p][j]);
        #pragma unroll
        for (int sub = 0; sub < 2; sub++) {
            size_t row = (size_t)(bm + ty*8 + 2*p + sub)*N + bn + tx*8;
            float o[8];
            #pragma unroll
            for (int j = 0; j < 8; j++) o[j] = (sub ? v[j].y : v[j].x) + bb[j];
            *(float4*)&C[row]     = *(float4*)&o[0];
            *(float4*)&C[row + 4] = *(float4*)&o[4];
        }
    }
}

// ====== 4-gate GEMM core: split-K, 512 thr, ping-pong smem, RBK=16 =====================
#define RBM 64
#define RBN 32
#define RBK 16
#define KSPLIT 256
#define NSTG (KSPLIT/RBK)             // 16
#define HS_LD 68
#define HS_FLOATS (RBK*HS_LD)         // 1088
#define WS4_FLOATS (RBK*RBN*4)        // 2048
#define HALF_FLOATS (2*HS_FLOATS + 2*WS4_FLOATS)   // 6272
#define SMEM_FLOATS (2*HALF_FLOATS)                // 12544 floats = 50176 B

__device__ __forceinline__ void gate_gemm_pp(const float* __restrict__ Abase,
                                             const float* __restrict__ W,
                                             int bm, int bn, int kbeg,
                                             float* __restrict__ base,
                                             u64t acc2[4][4]) {
    const int lt = threadIdx.x & 255;
    const int tx = lt & 31;        // col
    const int ty = lt >> 5;        // row-octet
    const int hm = lt >> 2;        // 0..63
    const int hk = (lt & 3) * 4;   // 0,4,8,12
    const int wr = lt >> 1;        // gate*32+col
    const int wk = (lt & 1) * 8;   // 0 or 8
    const int wg = wr >> 5;
    const int wn = wr & 31;

    const float* hp = Abase + (size_t)(bm + hm)*HH + kbeg + hk;
    const float* wp = W + (size_t)(wg*HH + bn + wn)*HH + kbeg + wk;

    float* HsA = base;
    float* HsB = base + HS_FLOATS;
    float* WsA = base + 2*HS_FLOATS;
    float* WsB = base + 2*HS_FLOATS + WS4_FLOATS;

    float4 ha  = *(const float4*)(hp);
    float4 wa0 = *(const float4*)(wp);
    float4 wa1 = *(const float4*)(wp + 4);

    // store stage 0
    HsA[(hk+0)*HS_LD + hm] = ha.x; HsA[(hk+1)*HS_LD + hm] = ha.y;
    HsA[(hk+2)*HS_LD + hm] = ha.z; HsA[(hk+3)*HS_LD + hm] = ha.w;
    {
        float w[8] = {wa0.x,wa0.y,wa0.z,wa0.w, wa1.x,wa1.y,wa1.z,wa1.w};
        #pragma unroll
        for (int j = 0; j < 8; j++) WsA[((wk+j)*RBN + wn)*4 + wg] = w[j];
    }
    __syncthreads();
    ha  = *(const float4*)(hp + RBK);
    wa0 = *(const float4*)(wp + RBK);
    wa1 = *(const float4*)(wp + RBK + 4);

    #pragma unroll 2
    for (int s = 0; s < NSTG; s++) {
        const float* H = (s & 1) ? HsB : HsA;
        const float* Wd = (s & 1) ? WsB : WsA;
        #pragma unroll
        for (int k = 0; k < RBK; k++) {
            ulonglong2 A0 = *(const ulonglong2*)&H[k*HS_LD + ty*8];
            ulonglong2 A1 = *(const ulonglong2*)&H[k*HS_LD + ty*8 + 4];
            float4 wv = *(const float4*)&Wd[(k*RBN + tx)*4];
            u64t wi  = pack2(wv.x, wv.x);
            u64t wf  = pack2(wv.y, wv.y);
            u64t wg2 = pack2(wv.z, wv.z);
            u64t wo  = pack2(wv.w, wv.w);
            fma2(acc2[0][0], A0.x, wi);  fma2(acc2[0][1], A0.y, wi);
            fma2(acc2[0][2], A1.x, wi);  fma2(acc2[0][3], A1.y, wi);
            fma2(acc2[1][0], A0.x, wf);  fma2(acc2[1][1], A0.y, wf);
            fma2(acc2[1][2], A1.x, wf);  fma2(acc2[1][3], A1.y, wf);
            fma2(acc2[2][0], A0.x, wg2); fma2(acc2[2][1], A0.y, wg2);
            fma2(acc2[2][2], A1.x, wg2); fma2(acc2[2][3], A1.y, wg2);
            fma2(acc2[3][0], A0.x, wo);  fma2(acc2[3][1], A0.y, wo);
            fma2(acc2[3][2], A1.x, wo);  fma2(acc2[3][3], A1.y, wo);
        }
        if (s < NSTG - 1) {
            float* Hn = (s & 1) ? HsA : HsB;
            float* Wn = (s & 1) ? WsA : WsB;
            Hn[(hk+0)*HS_LD + hm] = ha.x; Hn[(hk+1)*HS_LD + hm] = ha.y;
            Hn[(hk+2)*HS_LD + hm] = ha.z; Hn[(hk+3)*HS_LD + hm] = ha.w;
            {
                float w[8] = {wa0.x,wa0.y,wa0.z,wa0.w, wa1.x,wa1.y,wa1.z,wa1.w};
                #pragma unroll
                for (int j = 0; j < 8; j++) Wn[((wk+j)*RBN + wn)*4 + wg] = w[j];
            }
            __syncthreads();
            if (s < NSTG - 2) {
                ha  = *(const float4*)(hp + (s+2)*RBK);
                wa0 = *(const float4*)(wp + (s+2)*RBK);
                wa1 = *(const float4*)(wp + (s+2)*RBK + 4);
            }
        }
    }
}

// Merge half-1 partials into half-0 accumulators via smem.
__device__ __forceinline__ void ksplit_merge(float* __restrict__ smemAll,
                                             u64t acc2[4][4], int half) {
    u64t* red = reinterpret_cast<u64t*>(smemAll);
    const int lt = threadIdx.x & 255;
    __syncthreads();                      // mainloop has no trailing sync
    if (half == 1) {
        #pragma unroll
        for (int g = 0; g < 4; g++)
            #pragma unroll
            for (int p = 0; p < 4; p++)
                red[lt*16 + g*4 + p] = acc2[g][p];
    }
    __syncthreads();
    if (half == 0) {
        #pragma unroll
        for (int g = 0; g < 4; g++)
            #pragma unroll
            for (int p = 0; p < 4; p++)
                add2(acc2[g][p], red[lt*16 + g*4 + p]);
    }
}

// LSTM elementwise epilogue (half-0 threads: 8 rows x 1 col each)
__device__ __forceinline__ void lstm_epilogue(u64t acc2[4][4],
                                              const float* __restrict__ pre,
                                              const float* __restrict__ cin,
                                              float* __restrict__ cout,
                                              float* __restrict__ hout,
                                              int bm, int bn) {
    const int lt = threadIdx.x & 255;
    const int tx = lt & 31;
    const int ty = lt >> 5;
    const int n = bn + tx;
    #pragma unroll
    for (int p = 0; p < 4; p++) {
        float2 vi = unpack2(acc2[0][p]);
        float2 vf = unpack2(acc2[1][p]);
        float2 vg = unpack2(acc2[2][p]);
        float2 vo = unpack2(acc2[3][p]);
        #pragma unroll
        for (int sub = 0; sub < 2; sub++) {
            int b = bm + ty*8 + 2*p + sub;
            const float* pb = pre + (size_t)b*GG;
            float gi = pb[0*HH + n] + (sub ? vi.y : vi.x);
            float gf = pb[1*HH + n] + (sub ? vf.y : vf.x);
            float gg = pb[2*HH + n] + (sub ? vg.y : vg.x);
            float go = pb[3*HH + n] + (sub ? vo.y : vo.x);
            float cn = sigf(gf)*cin[(size_t)b*HH + n] + sigf(gi)*tanhf(gg);
            cout[(size_t)b*HH + n] = cn;
            hout[(size_t)b*HH + n] = sigf(go)*tanhf(cn);
        }
    }
}

// partial writer: outp[b, g*H+n] = acc + bias
__device__ __forceinline__ void part_store(u64t acc2[4][4],
                                           const float* __restrict__ bias,
                                           float* __restrict__ outp,
                                           int bm, int bn) {
    const int lt = threadIdx.x & 255;
    const int tx = lt & 31;
    const int ty = lt >> 5;
    const int n = bn + tx;
    #pragma unroll
    for (int g = 0; g < 4; g++) {
        float bv = bias[g*HH + n];
        #pragma unroll
        for (int p = 0; p < 4; p++) {
            float2 v = unpack2(acc2[g][p]);
            int b0 = bm + ty*8 + 2*p;
            outp[(size_t)(b0+0)*GG + g*HH + n] = v.x + bv;
            outp[(size_t)(b0+1)*GG + g*HH + n] = v.y + bv;
        }
    }
}

#define ZERO_ACC(acc2) { _Pragma("unroll") for (int g_ = 0; g_ < 4; g_++) { \
    _Pragma("unroll") for (int p_ = 0; p_ < 4; p_++) acc2[g_][p_] = 0ull; } }

// ---------------- encoder recurrent step (both dirs via grid.z) ----------------
struct DirArgs {
    const float* pre;
    const float* hin;
    const float* cin;
    float* cout;
    float* hout;
    const float* Whh;
};

__global__ __launch_bounds__(512, 1) void lstm_step2(DirArgs A0, DirArgs A1) {
    __shared__ __align__(16) float S[SMEM_FLOATS];
    DirArgs d = blockIdx.z ? A1 : A0;
    const int half = threadIdx.x >> 8;
    float* base = S + half*HALF_FLOATS;
    int bm = blockIdx.y * RBM;
    int bn = blockIdx.x * RBN;
    u64t acc2[4][4];
    ZERO_ACC(acc2);
    gate_gemm_pp(d.hin, d.Whh, bm, bn, half*KSPLIT, base, acc2);
    ksplit_merge(S, acc2, half);
    if (half == 0)
        lstm_epilogue(acc2, d.pre, d.cin, d.cout, d.hout, bm, bn);
}

// ---------------- decoder phase Y: cell1 (z=0) || part0' = dh0@Whh0 (z=1) --------------
__global__ __launch_bounds__(512, 1) void dec_Y(const float* __restrict__ dh0,
                                                const float* __restrict__ Wih1,
                                                const float* __restrict__ part1,
                                                float* __restrict__ dc1,
                                                float* __restrict__ dh1,
                                                const float* __restrict__ Whh0,
                                                const float* __restrict__ zerob,
                                                float* __restrict__ part0) {
    __shared__ __align__(16) float S[SMEM_FLOATS];
    const int half = threadIdx.x >> 8;
    float* base = S + half*HALF_FLOATS;
    int bm = blockIdx.y * RBM;
    int bn = blockIdx.x * RBN;
    u64t acc2[4][4];
    ZERO_ACC(acc2);
    if (blockIdx.z == 0) {
        gate_gemm_pp(dh0, Wih1, bm, bn, half*KSPLIT, base, acc2);
        ksplit_merge(S, acc2, half);
        if (half == 0) lstm_epilogue(acc2, part1, dc1, dc1, dh1, bm, bn);
    } else {
        gate_gemm_pp(dh0, Whh0, bm, bn, half*KSPLIT, base, acc2);
        ksplit_merge(S, acc2, half);
        if (half == 0) part_store(acc2, zerob, part0, bm, bn);
    }
}

// ---- decoder phase Z: logits+argmax+cell0 elementwise (z=0) || part1'=dh1@Whh1+b1 (z=1)
__global__ __launch_bounds__(512, 1) void dec_Z(const float* __restrict__ dh1,
                                                const float* __restrict__ Wout,
                                                const float* __restrict__ bout,
                                                const float* __restrict__ Whh1,
                                                const float* __restrict__ b1,
                                                float* __restrict__ part1,
                                                const float* __restrict__ Ptab,
                                                const float* __restrict__ part0,
                                                float* __restrict__ dc0,
                                                float* __restrict__ dh0,
                                                float* __restrict__ recon,
                                                int t) {
    __shared__ __align__(16) float S[SMEM_FLOATS];
    if (blockIdx.z == 1) {
        const int half = threadIdx.x >> 8;
        float* base = S + half*HALF_FLOATS;
        int bm = blockIdx.y * RBM;
        int bn = blockIdx.x * RBN;
        u64t acc2[4][4];
        ZERO_ACC(acc2);
        gate_gemm_pp(dh1, Whh1, bm, bn, half*KSPLIT, base, acc2);
        ksplit_merge(S, acc2, half);
        if (half == 0) part_store(acc2, b1, part1, bm, bn);
        return;
    }
    // role L: 64 blocks, 4 batch rows each
    const int tid = threadIdx.x;
    const int bid = blockIdx.y*16 + blockIdx.x;
    const int b0r = bid * 4;
    float* sh = S;                     // 4*512 dh1 rows
    float* sv = S + 4*HH;              // 4*128
    int*   si = (int*)(S + 4*HH + 4*VV);
    ((float4*)sh)[tid] = ((const float4*)(dh1 + (size_t)b0r*HH))[tid];   // 512 float4
    __syncthreads();
    const int v = tid & 127;
    const int r = tid >> 7;
    const float4* w4 = (const float4*)(Wout + (size_t)v*HH);
    const float* shr = sh + r*HH;
    float acc = bout[v];
    #pragma unroll 8
    for (int k = 0; k < HH/4; k++) {
        float4 wv = w4[k];
        float4 s4 = *(const float4*)&shr[k*4];
        acc += s4.x*wv.x + s4.y*wv.y + s4.z*wv.z + s4.w*wv.w;
    }
    recon[(size_t)(b0r+r)*TT*VV + (size_t)t*VV + v] = acc;
    sv[r*VV + v] = acc;
    si[r*VV + v] = v;
    __syncthreads();
    for (int s2 = 64; s2 > 0; s2 >>= 1) {
        if (v < s2) {
            float ov = sv[r*VV + v + s2]; int oi = si[r*VV + v + s2];
            if (ov > sv[r*VV + v] || (ov == sv[r*VV + v] && oi < si[r*VV + v])) {
                sv[r*VV + v] = ov; si[r*VV + v] = oi;
            }
        }
        __syncthreads();
    }
    // cell0 elementwise for row b = b0r + r, cols v*4..v*4+3, using fresh token
    const int tk = si[r*VV];
    const int b = b0r + r;
    const int h0c = v * 4;
    const float* pt = Ptab + (size_t)tk*GG;
    const float* p0 = part0 + (size_t)b*GG;
    float4 pi = *(const float4*)&pt[0*HH + h0c]; float4 qi = *(const float4*)&p0[0*HH + h0c];
    float4 pf = *(const float4*)&pt[1*HH + h0c]; float4 qf = *(const float4*)&p0[1*HH + h0c];
    float4 pg = *(const float4*)&pt[2*HH + h0c]; float4 qg = *(const float4*)&p0[2*HH + h0c];
    float4 po = *(const float4*)&pt[3*HH + h0c]; float4 qo = *(const float4*)&p0[3*HH + h0c];
    float4 c4 = *(const float4*)&dc0[(size_t)b*HH + h0c];
    float gi[4] = {pi.x+qi.x, pi.y+qi.y, pi.z+qi.z, pi.w+qi.w};
    float gf[4] = {pf.x+qf.x, pf.y+qf.y, pf.z+qf.z, pf.w+qf.w};
    float gg[4] = {pg.x+qg.x, pg.y+qg.y, pg.z+qg.z, pg.w+qg.w};
    float go[4] = {po.x+qo.x, po.y+qo.y, po.z+qo.z, po.w+qo.w};
    float cc[4] = {c4.x, c4.y, c4.z, c4.w};
    float co[4], ho[4];
    #pragma unroll
    for (int j = 0; j < 4; j++) {
        float cn = sigf(gf[j])*cc[j] + sigf(gi[j])*tanhf(gg[j]);
        co[j] = cn;
        ho[j] = sigf(go[j])*tanhf(cn);
    }
    *(float4*)&dc0[(size_t)b*HH + h0c] = make_float4(co[0], co[1], co[2], co[3]);
    *(float4*)&dh0[(size_t)b*HH + h0c] = make_float4(ho[0], ho[1], ho[2], ho[3]);
}

// ---------------- cell0 at t=0 (token fixed = 1) ----------------
__global__ __launch_bounds__(128) void cell0_init_kernel(const float* __restrict__ Ptab,
                                                         const float* __restrict__ part0,
                                                         float* __restrict__ dc0,
                                                         float* __restrict__ dh0) {
    const int b = blockIdx.x;
    const int h0c = threadIdx.x * 4;
    const float* pt = Ptab + (size_t)1*GG;
    const float* p0 = part0 + (size_t)b*GG;
    float4 pi = *(const float4*)&pt[0*HH + h0c]; float4 qi = *(const float4*)&p0[0*HH + h0c];
    float4 pf = *(const float4*)&pt[1*HH + h0c]; float4 qf = *(const float4*)&p0[1*HH + h0c];
    float4 pg = *(const float4*)&pt[2*HH + h0c]; float4 qg = *(const float4*)&p0[2*HH + h0c];
    float4 po = *(const float4*)&pt[3*HH + h0c]; float4 qo = *(const float4*)&p0[3*HH + h0c];
    float4 c4 = *(const float4*)&dc0[(size_t)b*HH + h0c];
    float gi[4] = {pi.x+qi.x, pi.y+qi.y, pi.z+qi.z, pi.w+qi.w};
    float gf[4] = {pf.x+qf.x, pf.y+qf.y, pf.z+qf.z, pf.w+qf.w};
    float gg[4] = {pg.x+qg.x, pg.y+qg.y, pg.z+qg.z, pg.w+qg.w};
    float go[4] = {po.x+qo.x, po.y+qo.y, po.z+qo.z, po.w+qo.w};
    float cc[4] = {c4.x, c4.y, c4.z, c4.w};
    float co[4], ho[4];
    #pragma unroll
    for (int j = 0; j < 4; j++) {
        float cn = sigf(gf[j])*cc[j] + sigf(gi[j])*tanhf(gg[j]);
        co[j] = cn;
        ho[j] = sigf(go[j])*tanhf(cn);
    }
    *(float4*)&dc0[(size_t)b*HH + h0c] = make_float4(co[0], co[1], co[2], co[3]);
    *(float4*)&dh0[(size_t)b*HH + h0c] = make_float4(ho[0], ho[1], ho[2], ho[3]);
}

// ---------------- mu/logvar heads ----------------
__global__ __launch_bounds__(256) void head_kernel(const float* __restrict__ hf,
                                                   const float* __restrict__ hb,
                                                   const float* __restrict__ Wmu,
                                                   const float* __restrict__ bmu,
                                                   const float* __restrict__ Wlv,
                                                   const float* __restrict__ blv,
                                                   float* __restrict__ out_mu,
                                                   float* __restrict__ out_lv,
                                                   float* __restrict__ zbuf) {
    int b = blockIdx.x;
    int tid = threadIdx.x;
    __shared__ float sh[2*HH];
    for (int i = tid; i < HH; i += 256) {
        sh[i]      = hf[b*HH + i];
        sh[HH + i] = hb[b*HH + i];
    }
    __syncthreads();
    const float* W;
    float acc;
    int l;
    if (tid < LL) { l = tid;      W = Wmu + (size_t)l*2*HH; acc = bmu[l]; }
    else          { l = tid - LL; W = Wlv + (size_t)l*2*HH; acc = blv[l]; }
    #pragma unroll 8
    for (int k = 0; k < 2*HH; k++) acc += sh[k]*W[k];
    if (tid < LL) { out_mu[b*LL + l] = acc; zbuf[b*LL + l] = acc; }
    else          { out_lv[b*LL + l] = acc; }
}

// ---------------- decoder init ----------------
__global__ __launch_bounds__(512) void dec_init_kernel(const float* __restrict__ z,
                                                       const float* __restrict__ W,
                                                       const float* __restrict__ bias,
                                                       float* __restrict__ h0,
                                                       float* __restrict__ h1,
                                                       float* __restrict__ c0,
                                                       float* __restrict__ c1) {
    int b = blockIdx.x;
    int tid = threadIdx.x;
    __shared__ float sz[LL];
    if (tid < LL) sz[tid] = z[b*LL + tid];
    __syncthreads();
    float acc = bias[tid];
    const float* w = W + (size_t)tid*LL;
    #pragma unroll 8
    for (int k = 0; k < LL; k++) acc += sz[k]*w[k];
    h0[b*HH + tid] = acc;
    h1[b*HH + tid] = acc;
    c0[b*HH + tid] = 0.0f;
    c1[b*HH + tid] = 0.0f;
}

// =================================== host launcher ====================================
extern "C" void kernel_launch(void* const* d_in, const int* in_sizes, int n_in,
                              void* d_out, int out_size) {
    const int*   x           = (const int*)  d_in[0];
    const float* emb         = (const float*)d_in[1];
    const float* enc_wih_l0  = (const float*)d_in[2];
    const float* enc_whh_l0  = (const float*)d_in[3];
    const float* enc_b_l0    = (const float*)d_in[4];
    const float* enc_wih_l1  = (const float*)d_in[5];
    const float* enc_whh_l1  = (const float*)d_in[6];
    const float* enc_b_l1    = (const float*)d_in[7];
    const float* fc_mu_w     = (const float*)d_in[8];
    const float* fc_mu_b     = (const float*)d_in[9];
    const float* fc_lv_w     = (const float*)d_in[10];
    const float* fc_lv_b     = (const float*)d_in[11];
    const float* dec_in_w    = (const float*)d_in[12];
    const float* dec_in_b    = (const float*)d_in[13];
    const float* dec_wih     = (const float*)d_in[14];
    const float* dec_whh     = (const float*)d_in[15];
    const float* dec_b       = (const float*)d_in[16];
    const float* dec_out_w   = (const float*)d_in[17];
    const float* dec_out_b   = (const float*)d_in[18];

    float* out       = (float*)d_out;
    float* out_recon = out;
    float* out_mu    = out + (size_t)BB*TT*VV;
    float* out_lv    = out_mu + (size_t)BB*LL;

    float *seq, *seq1, *preF, *preB, *y0f, *y0b, *y1f, *y1b;
    float *c0f, *c0b, *c1f, *c1b, *zeros, *zbuf, *dh0, *dh1, *dc0, *dc1;
    float *part0, *part1, *ptab;
    cudaGetSymbolAddress((void**)&seq,   g_seq);
    cudaGetSymbolAddress((void**)&seq1,  g_seq1);
    cudaGetSymbolAddress((void**)&preF,  g_preF);
    cudaGetSymbolAddress((void**)&preB,  g_preB);
    cudaGetSymbolAddress((void**)&y0f,   g_y0f);
    cudaGetSymbolAddress((void**)&y0b,   g_y0b);
    cudaGetSymbolAddress((void**)&y1f,   g_y1f);
    cudaGetSymbolAddress((void**)&y1b,   g_y1b);
    cudaGetSymbolAddress((void**)&c0f,   g_c0f);
    cudaGetSymbolAddress((void**)&c0b,   g_c0b);
    cudaGetSymbolAddress((void**)&c1f,   g_c1f);
    cudaGetSymbolAddress((void**)&c1b,   g_c1b);
    cudaGetSymbolAddress((void**)&zeros, g_zeros);
    cudaGetSymbolAddress((void**)&zbuf,  g_z);
    cudaGetSymbolAddress((void**)&dh0,   g_dh0);
    cudaGetSymbolAddress((void**)&dh1,   g_dh1);
    cudaGetSymbolAddress((void**)&dc0,   g_dc0);
    cudaGetSymbolAddress((void**)&dc1,   g_dc1);
    cudaGetSymbolAddress((void**)&part0, g_part0);
    cudaGetSymbolAddress((void**)&part1, g_part1);
    cudaGetSymbolAddress((void**)&ptab,  g_ptab);

    const float* dWih0 = dec_wih;
    const float* dWih1 = dec_wih + (size_t)GG*HH;
    const float* dWhh0 = dec_whh;
    const float* dWhh1 = dec_whh + (size_t)GG*HH;
    const float* db0   = dec_b;
    const float* db1   = dec_b + GG;

    // 1) embedding + decoder token table (independent)
    embed_kernel<<<2048, 256>>>(x, emb, seq);
    sgemm_bias_f<<<dim3(GG/PBN, VV/PBM), 256>>>(emb, dWih0, db0, ptab, VV, GG, HH);

    // 2) encoder layer 0: pre-GEMMs + steps
    dim3 preGrd(GG/PBN, (TT*BB)/PBM);
    sgemm_bias_f<<<preGrd, 256>>>(seq, enc_wih_l0,                 enc_b_l0,      preF, TT*BB, GG, HH);
    sgemm_bias_f<<<preGrd, 256>>>(seq, enc_wih_l0 + (size_t)GG*HH, enc_b_l0 + GG, preB, TT*BB, GG, HH);

    dim3 stepGrd(HH/RBN, BB/RBM, 2);   // (16,4,2) = 128 blocks x 512 threads
    for (int s = 0; s < TT; s++) {
        int tf = s, tb = TT-1-s;
        DirArgs df = { preF + (size_t)tf*BB*GG,
                       (s ? y0f + (size_t)(tf-1)*BB*HH : zeros),
                       (s ? c0f : zeros), c0f,
                       y0f + (size_t)tf*BB*HH,
                       enc_whh_l0 };
        DirArgs db = { preB + (size_t)tb*BB*GG,
                       (s ? y0b + (size_t)(tb+1)*BB*HH : zeros),
                       (s ? c0b : zeros), c0b,
                       y0b + (size_t)tb*BB*HH,
                       enc_whh_l0 + (size_t)GG*HH };
        lstm_step2<<<stepGrd, 512>>>(df, db);
    }

    // 3) encoder layer 1
    concat_kernel<<<2048, 256>>>(y0f, y0b, seq1);
    sgemm_bias_f<<<preGrd, 256>>>(seq1, enc_wih_l1,                   enc_b_l1,      preF, TT*BB, GG, 2*HH);
    sgemm_bias_f<<<preGrd, 256>>>(seq1, enc_wih_l1 + (size_t)GG*2*HH, enc_b_l1 + GG, preB, TT*BB, GG, 2*HH);
    for (int s = 0; s < TT; s++) {
        int tf = s, tb = TT-1-s;
        DirArgs df = { preF + (size_t)tf*BB*GG,
                       (s ? y1f + (size_t)(tf-1)*BB*HH : zeros),
                       (s ? c1f : zeros), c1f,
                       y1f + (size_t)tf*BB*HH,
                       enc_whh_l1 };
        DirArgs db = { preB + (size_t)tb*BB*GG,
                       (s ? y1b + (size_t)(tb+1)*BB*HH : zeros),
                       (s ? c1b : zeros), c1b,
                       y1b + (size_t)tb*BB*HH,
                       enc_whh_l1 + (size_t)GG*HH };
        lstm_step2<<<stepGrd, 512>>>(df, db);
    }

    // 4) heads
    head_kernel<<<BB, 256>>>(y1f + (size_t)(TT-1)*BB*HH, y1b,
                             fc_mu_w, fc_mu_b, fc_lv_w, fc_lv_b,
                             out_mu, out_lv, zbuf);

    // 5) decoder init: h/c states, partials, cell0(t=0) with start token 1
    dec_init_kernel<<<BB, 512>>>(zbuf, dec_in_w, dec_in_b, dh0, dh1, dc0, dc1);
    dim3 partGrd(GG/PBN, BB/PBM);
    sgemm_bias_f<<<partGrd, 256>>>(dh0, dWhh0, zeros, part0, BB, GG, HH);   // bias-less (b0 in Ptab)
    sgemm_bias_f<<<partGrd, 256>>>(dh1, dWhh1, db1,   part1, BB, GG, HH);
    cell0_init_kernel<<<BB, 128>>>(ptab, part0, dc0, dh0);

    // 6) autoregressive decode: 2 launches per step
    dim3 decGrd(HH/RBN, BB/RBM, 2);    // (16,4,2) = 128 blocks
    for (int t = 0; t < TT; t++) {
        // Y: cell1 (dh0@Wih1 + part1 -> dh1,dc1)  ||  part0' = dh0@Whh0
        dec_Y<<<decGrd, 512>>>(dh0, dWih1, part1, dc1, dh1, dWhh0, zeros, part0);
        // Z: logits+argmax+cell0 (-> recon[:,t,:], dh0,dc0)  ||  part1' = dh1@Whh1 + b1
        dec_Z<<<decGrd, 512>>>(dh1, dec_out_w, dec_out_b, dWhh1, db1, part1,
                               ptab, part0, dc0, dh0, out_recon, t);
    }
}

// round 8
// speedup vs baseline: 1.3993x; 1.1940x over previous
#include <cuda_runtime.h>
#include <math.h>

// ---------------- problem constants ----------------
#define TT 128
#define BB 256
#define HH 512
#define GG 2048
#define VV 128
#define LL 128
#define LDH (TT*BB)          // row stride of big transposed activation buffers

typedef unsigned long long u64t;

__device__ __forceinline__ u64t pack2(float x, float y) {
    u64t r; asm("mov.b64 %0, {%1, %2};" : "=l"(r) : "f"(x), "f"(y)); return r;
}
__device__ __forceinline__ void fma2(u64t& d, u64t a, u64t b) {
    asm("fma.rn.f32x2 %0, %1, %2, %0;" : "+l"(d) : "l"(a), "l"(b));
}
__device__ __forceinline__ void add2(u64t& d, u64t a) {
    asm("add.rn.f32x2 %0, %0, %1;" : "+l"(d) : "l"(a));
}
__device__ __forceinline__ float2 unpack2(u64t v) {
    float2 r; asm("mov.b64 {%0, %1}, %2;" : "=f"(r.x), "=f"(r.y) : "l"(v)); return r;
}
__device__ __forceinline__ unsigned smem_u32(const void* p) {
    return (unsigned)__cvta_generic_to_shared(p);
}
#define CP16(dst, src) asm volatile("cp.async.ca.shared.global [%0], [%1], 16;" :: "r"(dst), "l"((const void*)(src)) : "memory")
#define CP_COMMIT      asm volatile("cp.async.commit_group;" ::: "memory")
#define CP_WAIT1       asm volatile("cp.async.wait_group 1;" ::: "memory")
#define CP_WAIT0       asm volatile("cp.async.wait_group 0;" ::: "memory")

// ---------------- device scratch (16B aligned) ----------------
__device__ __align__(16) float g_seqT [HH*LDH];        // emb(x) transposed [k][t*B+b]
__device__ __align__(16) float g_seq1T[2*HH*LDH];      // layer0 outputs (fwd rows 0..511, bwd 512..1023)
__device__ __align__(16) float g_y1fT [HH*LDH];
__device__ __align__(16) float g_y1bT [HH*LDH];
__device__ __align__(16) float g_preF [TT*BB*GG];
__device__ __align__(16) float g_preB [TT*BB*GG];
__device__ __align__(16) float g_c0fT [HH*BB];
__device__ __align__(16) float g_c0bT [HH*BB];
__device__ __align__(16) float g_c1fT [HH*BB];
__device__ __align__(16) float g_c1bT [HH*BB];
__device__ __align__(16) float g_zeros[HH*BB];          // never written
__device__ __align__(16) float g_z    [BB*LL];
__device__ __align__(16) float g_dh0T [HH*BB];
__device__ __align__(16) float g_dh1T [HH*BB];
__device__ __align__(16) float g_dh1n [BB*HH];          // normal layout for logits
__device__ __align__(16) float g_dc0  [BB*HH];          // normal (only cell0 touches)
__device__ __align__(16) float g_dc1T [HH*BB];
__device__ __align__(16) float g_part0[BB*GG];
__device__ __align__(16) float g_part1[BB*GG];
__device__ __align__(16) float g_ptab [VV*GG];
__device__ __align__(16) float g_embT [HH*VV];
__device__ __align__(16) float g_wt   [9*1024*1024];    // plain WT [k][n] buffers
__device__ __align__(16) float g_wt4  [7*1024*1024];    // interleaved [k][n*4+g]

__device__ __forceinline__ float sigf(float v) { return 1.0f / (1.0f + expf(-v)); }

// ---------------- transforms ----------------
__global__ void wt_kernel(const float* __restrict__ in, float* __restrict__ out,
                          int N, int K) {   // out[k*N+n] = in[n*K+k]
    int total = N*K;
    for (int i = blockIdx.x*blockDim.x + threadIdx.x; i < total; i += gridDim.x*blockDim.x) {
        int n = i % N; int k = i / N;
        out[i] = in[(size_t)n*K + k];
    }
}
__global__ void wt4_kernel(const float* __restrict__ in, float* __restrict__ out) {
    // out[k*2048 + n*4 + g] = in[(g*512+n)*512 + k]
    int total = HH*GG;
    for (int i = blockIdx.x*blockDim.x + threadIdx.x; i < total; i += gridDim.x*blockDim.x) {
        int g = i & 3; int n = (i >> 2) & 511; int k = i >> 11;
        out[i] = in[((size_t)(g*HH + n))*HH + k];
    }
}
__global__ void embT_kernel(const int* __restrict__ x, const float* __restrict__ emb,
                            float* __restrict__ seqT) {
    int total = HH*LDH;
    for (int i = blockIdx.x*blockDim.x + threadIdx.x; i < total; i += gridDim.x*blockDim.x) {
        int k = i / LDH; int m = i % LDH;
        int t = m / BB;  int b = m % BB;
        seqT[i] = emb[x[b*TT + t]*HH + k];
    }
}

// ================= sgemm_ca: C[M,N] = AT^T @ WT + bias; AT[k][M], WT[k][N] =============
// 128x128 tile, BK=16, 256 threads, 2 blocks/SM, cp.async staging (no transpose).
__global__ __launch_bounds__(256, 2) void sgemm_ca(const float* __restrict__ AT,
                                                   const float* __restrict__ WT,
                                                   const float* __restrict__ bias,
                                                   float* __restrict__ C,
                                                   int M, int N, int K) {
    __shared__ __align__(16) float S[2*4096];   // 2 bufs x (As 2048 + Ws 2048)
    const int bm = blockIdx.y * 128;
    const int bn = blockIdx.x * 128;
    const int tid = threadIdx.x;
    const int tx = tid % 16;
    const int ty = tid / 16;
    const int NS = K / 16;

    const int ck  = tid >> 5;            // 0..7
    const int co  = (tid & 31) * 4;      // 0..124
    const float* asrc = AT + (size_t)ck*M + bm + co;
    const float* wsrc = WT + (size_t)ck*N + bn + co;
    unsigned sb = smem_u32(S);
    unsigned adst = sb + ((ck*128 + co) << 2);
    unsigned wdst = sb + ((2048 + ck*128 + co) << 2);

    #define PRE_ISSUE(s) { unsigned o_ = ((s)&1)*16384u; size_t ka_ = (size_t)(s)*16*M, kw_ = (size_t)(s)*16*N; \
        CP16(adst + o_, asrc + ka_); CP16(adst + o_ + 4096u, asrc + ka_ + 8*(size_t)M); \
        CP16(wdst + o_, wsrc + kw_); CP16(wdst + o_ + 4096u, wsrc + kw_ + 8*(size_t)N); CP_COMMIT; }

    u64t acc2[4][8];
    #pragma unroll
    for (int p = 0; p < 4; p++)
        #pragma unroll
        for (int j = 0; j < 8; j++) acc2[p][j] = 0ull;

    PRE_ISSUE(0);
    PRE_ISSUE(1);
    CP_WAIT1;
    __syncthreads();

    for (int s = 0; s < NS; s++) {
        const float* Bq = S + (s & 1)*4096;
        #pragma unroll
        for (int k = 0; k < 16; k++) {
            ulonglong2 A0 = *(const ulonglong2*)&Bq[k*128 + ty*8];
            ulonglong2 A1 = *(const ulonglong2*)&Bq[k*128 + ty*8 + 4];
            u64t apair[4] = {A0.x, A0.y, A1.x, A1.y};
            float w[8];
            *(float4*)&w[0] = *(const float4*)&Bq[2048 + k*128 + tx*8];
            *(float4*)&w[4] = *(const float4*)&Bq[2048 + k*128 + tx*8 + 4];
            #pragma unroll
            for (int j = 0; j < 8; j++) {
                u64t w2 = pack2(w[j], w[j]);
                #pragma unroll
                for (int p = 0; p < 4; p++) fma2(acc2[p][j], apair[p], w2);
            }
        }
        if (s == NS - 1) break;
        __syncthreads();
        if (s + 2 < NS) { PRE_ISSUE(s+2); CP_WAIT1; }
        else            { CP_WAIT0; }
        __syncthreads();
    }

    float bb[8];
    *(float4*)&bb[0] = *(const float4*)(bias + bn + tx*8);
    *(float4*)&bb[4] = *(const float4*)(bias + bn + tx*8 + 4);
    #pragma unroll
    for (int p = 0; p < 4; p++) {
        float2 v[8];
        #pragma unroll
        for (int j = 0; j < 8; j++) v[j] = unpack2(acc2[p][j]);
        #pragma unroll
        for (int sub = 0; sub < 2; sub++) {
            size_t row = (size_t)(bm + ty*8 + 2*p + sub)*N + bn + tx*8;
            float o[8];
            #pragma unroll
            for (int j = 0; j < 8; j++) o[j] = (sub ? v[j].y : v[j].x) + bb[j];
            *(float4*)&C[row]     = *(float4*)&o[0];
            *(float4*)&C[row + 4] = *(float4*)&o[4];
        }
    }
    #undef PRE_ISSUE
}

// ====== gate GEMM core: split-K (512 thr), cp.async, operands K-major ==================
// A = hT[k][m] (row stride lda), W = WT4[k][n*4+g]. Tile 64 b x 32 n x 4 g per half.
#define NSTG 16
#define GBUF 3072           // floats per buf per half (Hs 1024 + Ws 2048)
#define GHALF (2*GBUF)      // 6144 floats per half
#define GSMEM (2*GHALF)     // 12288 floats = 48 KB

__device__ __forceinline__ void gate_gemm_ca(const float* __restrict__ hT, int lda,
                                             const float* __restrict__ WT4,
                                             int bm, int bn, int kbeg,
                                             float* __restrict__ base,
                                             u64t acc2[4][4]) {
    const int lt = threadIdx.x & 255;
    const int tx = lt & 31;
    const int ty = lt >> 5;

    const float* hsrc = hT + (size_t)(kbeg + (lt >> 4))*lda + bm + (lt & 15)*4;
    const float* wsrc = WT4 + (size_t)(kbeg + (lt >> 5))*GG + (size_t)bn*4 + (lt & 31)*4;
    unsigned sb = smem_u32(base);
    unsigned hdst = sb + (((lt >> 4)*64 + (lt & 15)*4) << 2);
    unsigned wdst = sb + ((1024 + (lt >> 5)*128 + (lt & 31)*4) << 2);

    #define G_ISSUE(s) { unsigned o_ = ((s)&1)*(GBUF*4u); size_t kh_ = (size_t)(s)*16*lda, kw_ = (size_t)(s)*16*GG; \
        CP16(hdst + o_, hsrc + kh_); \
        CP16(wdst + o_, wsrc + kw_); CP16(wdst + o_ + 4096u, wsrc + kw_ + 8*(size_t)GG); CP_COMMIT; }

    G_ISSUE(0);
    G_ISSUE(1);
    CP_WAIT1;
    __syncthreads();

    #pragma unroll
    for (int s = 0; s < NSTG; s++) {
        const float* Bq = base + (s & 1)*GBUF;
        #pragma unroll
        for (int k = 0; k < 16; k++) {
            ulonglong2 A0 = *(const ulonglong2*)&Bq[k*64 + ty*8];
            ulonglong2 A1 = *(const ulonglong2*)&Bq[k*64 + ty*8 + 4];
            float4 wv = *(const float4*)&Bq[1024 + k*128 + tx*4];
            u64t wi  = pack2(wv.x, wv.x);
            u64t wf  = pack2(wv.y, wv.y);
            u64t wg2 = pack2(wv.z, wv.z);
            u64t wo  = pack2(wv.w, wv.w);
            fma2(acc2[0][0], A0.x, wi);  fma2(acc2[0][1], A0.y, wi);
            fma2(acc2[0][2], A1.x, wi);  fma2(acc2[0][3], A1.y, wi);
            fma2(acc2[1][0], A0.x, wf);  fma2(acc2[1][1], A0.y, wf);
            fma2(acc2[1][2], A1.x, wf);  fma2(acc2[1][3], A1.y, wf);
            fma2(acc2[2][0], A0.x, wg2); fma2(acc2[2][1], A0.y, wg2);
            fma2(acc2[2][2], A1.x, wg2); fma2(acc2[2][3], A1.y, wg2);
            fma2(acc2[3][0], A0.x, wo);  fma2(acc2[3][1], A0.y, wo);
            fma2(acc2[3][2], A1.x, wo);  fma2(acc2[3][3], A1.y, wo);
        }
        if (s == NSTG - 1) break;
        __syncthreads();
        if (s + 2 < NSTG) { G_ISSUE(s+2); CP_WAIT1; }
        else              { CP_WAIT0; }
        __syncthreads();
    }
    #undef G_ISSUE
}

__device__ __forceinline__ void ksplit_merge(float* __restrict__ smemAll,
                                             u64t acc2[4][4], int half) {
    u64t* red = reinterpret_cast<u64t*>(smemAll);
    const int lt = threadIdx.x & 255;
    __syncthreads();
    if (half == 1) {
        #pragma unroll
        for (int g = 0; g < 4; g++)
            #pragma unroll
            for (int p = 0; p < 4; p++)
                red[lt*16 + g*4 + p] = acc2[g][p];
    }
    __syncthreads();
    if (half == 0) {
        #pragma unroll
        for (int g = 0; g < 4; g++)
            #pragma unroll
            for (int p = 0; p < 4; p++)
                add2(acc2[g][p], red[lt*16 + g*4 + p]);
    }
}

// Epilogue: transposed c/h; optional normal h write. (half-0 threads: 8 rows x 1 col)
__device__ __forceinline__ void lstm_epiT(u64t acc2[4][4],
                                          const float* __restrict__ pre,
                                          const float* __restrict__ cinT,
                                          float* __restrict__ coutT,
                                          float* __restrict__ houtT, int ldh,
                                          float* __restrict__ houtN,
                                          int bm, int bn) {
    const int lt = threadIdx.x & 255;
    const int tx = lt & 31;
    const int ty = lt >> 5;
    const int n  = bn + tx;
    const int b0 = bm + ty*8;
    float cv[8], hv[8], co[8];
    *(float4*)&cv[0] = *(const float4*)&cinT[(size_t)n*BB + b0];
    *(float4*)&cv[4] = *(const float4*)&cinT[(size_t)n*BB + b0 + 4];
    #pragma unroll
    for (int p = 0; p < 4; p++) {
        float2 vi = unpack2(acc2[0][p]);
        float2 vf = unpack2(acc2[1][p]);
        float2 vg = unpack2(acc2[2][p]);
        float2 vo = unpack2(acc2[3][p]);
        #pragma unroll
        for (int sub = 0; sub < 2; sub++) {
            int idx = 2*p + sub;
            int b = b0 + idx;
            const float* pb = pre + (size_t)b*GG;
            float gi = pb[0*HH + n] + (sub ? vi.y : vi.x);
            float gf = pb[1*HH + n] + (sub ? vf.y : vf.x);
            float gg = pb[2*HH + n] + (sub ? vg.y : vg.x);
            float go = pb[3*HH + n] + (sub ? vo.y : vo.x);
            float cn = sigf(gf)*cv[idx] + sigf(gi)*tanhf(gg);
            co[idx] = cn;
            hv[idx] = sigf(go)*tanhf(cn);
        }
    }
    *(float4*)&coutT[(size_t)n*BB + b0]     = *(float4*)&co[0];
    *(float4*)&coutT[(size_t)n*BB + b0 + 4] = *(float4*)&co[4];
    *(float4*)&houtT[(size_t)n*ldh + b0]     = *(float4*)&hv[0];
    *(float4*)&houtT[(size_t)n*ldh + b0 + 4] = *(float4*)&hv[4];
    if (houtN) {
        #pragma unroll
        for (int i = 0; i < 8; i++) houtN[(size_t)(b0+i)*HH + n] = hv[i];
    }
}

__device__ __forceinline__ void part_store(u64t acc2[4][4],
                                           const float* __restrict__ bias,
                                           float* __restrict__ outp,
                                           int bm, int bn) {
    const int lt = threadIdx.x & 255;
    const int tx = lt & 31;
    const int ty = lt >> 5;
    const int n = bn + tx;
    #pragma unroll
    for (int g = 0; g < 4; g++) {
        float bv = bias[g*HH + n];
        #pragma unroll
        for (int p = 0; p < 4; p++) {
            float2 v = unpack2(acc2[g][p]);
            int b0 = bm + ty*8 + 2*p;
            outp[(size_t)(b0+0)*GG + g*HH + n] = v.x + bv;
            outp[(size_t)(b0+1)*GG + g*HH + n] = v.y + bv;
        }
    }
}

#define ZERO_ACC(a) { _Pragma("unroll") for (int g_=0; g_<4; g_++) { \
    _Pragma("unroll") for (int p_=0; p_<4; p_++) (a)[g_][p_] = 0ull; } }

// ---------------- encoder recurrent step (both dirs via grid.z) ----------------
struct DirT {
    const float* pre;
    const float* hinT; int lda;
    const float* cinT;
    float* coutT;
    float* houtT;
    const float* WT4;
};

__global__ __launch_bounds__(512, 1) void lstm_stepT(DirT A0, DirT A1) {
    __shared__ __align__(16) float S[GSMEM];
    DirT d = blockIdx.z ? A1 : A0;
    const int half = threadIdx.x >> 8;
    float* base = S + half*GHALF;
    int bm = blockIdx.y * 64;
    int bn = blockIdx.x * 32;
    u64t acc2[4][4];
    ZERO_ACC(acc2);
    gate_gemm_ca(d.hinT, d.lda, d.WT4, bm, bn, half*256, base, acc2);
    ksplit_merge(S, acc2, half);
    if (half == 0)
        lstm_epiT(acc2, d.pre, d.cinT, d.coutT, d.houtT, LDH, nullptr, bm, bn);
}

// ---------------- decoder phase Y: cell1 (z=0) || part0' = dh0@Whh0 (z=1) --------------
__global__ __launch_bounds__(512, 1) void dec_Y(const float* __restrict__ dh0T,
                                                const float* __restrict__ w4ih1,
                                                const float* __restrict__ part1,
                                                float* __restrict__ dc1T,
                                                float* __restrict__ dh1T,
                                                float* __restrict__ dh1n,
                                                const float* __restrict__ w4hh0,
                                                const float* __restrict__ zerob,
                                                float* __restrict__ part0) {
    __shared__ __align__(16) float S[GSMEM];
    const int half = threadIdx.x >> 8;
    float* base = S + half*GHALF;
    int bm = blockIdx.y * 64;
    int bn = blockIdx.x * 32;
    u64t acc2[4][4];
    ZERO_ACC(acc2);
    if (blockIdx.z == 0) {
        gate_gemm_ca(dh0T, BB, w4ih1, bm, bn, half*256, base, acc2);
        ksplit_merge(S, acc2, half);
        if (half == 0) lstm_epiT(acc2, part1, dc1T, dc1T, dh1T, BB, dh1n, bm, bn);
    } else {
        gate_gemm_ca(dh0T, BB, w4hh0, bm, bn, half*256, base, acc2);
        ksplit_merge(S, acc2, half);
        if (half == 0) part_store(acc2, zerob, part0, bm, bn);
    }
}

// ---- decoder phase Z: logits+argmax+cell0 (z=0) || part1' = dh1@Whh1 + b1 (z=1) -------
__global__ __launch_bounds__(512, 1) void dec_Z(const float* __restrict__ dh1T,
                                                const float* __restrict__ dh1n,
                                                const float* __restrict__ Wout,
                                                const float* __restrict__ bout,
                                                const float* __restrict__ w4hh1,
                                                const float* __restrict__ b1,
                                                float* __restrict__ part1,
                                                const float* __restrict__ Ptab,
                                                const float* __restrict__ part0,
                                                float* __restrict__ dc0,
                                                float* __restrict__ dh0T,
                                                float* __restrict__ recon,
                                                int t) {
    __shared__ __align__(16) float S[GSMEM];
    if (blockIdx.z == 1) {
        const int half = threadIdx.x >> 8;
        float* base = S + half*GHALF;
        int bm = blockIdx.y * 64;
        int bn = blockIdx.x * 32;
        u64t acc2[4][4];
        ZERO_ACC(acc2);
        gate_gemm_ca(dh1T, BB, w4hh1, bm, bn, half*256, base, acc2);
        ksplit_merge(S, acc2, half);
        if (half == 0) part_store(acc2, b1, part1, bm, bn);
        return;
    }
    const int tid = threadIdx.x;
    const int bid = blockIdx.y*16 + blockIdx.x;
    const int b0r = bid * 4;
    float* sh = S;
    float* sv = S + 4*HH;
    int*   si = (int*)(S + 4*HH + 4*VV);
    ((float4*)sh)[tid] = ((const float4*)(dh1n + (size_t)b0r*HH))[tid];
    __syncthreads();
    const int v = tid & 127;
    const int r = tid >> 7;
    const float4* w4 = (const float4*)(Wout + (size_t)v*HH);
    const float* shr = sh + r*HH;
    float acc = bout[v];
    #pragma unroll 8
    for (int k = 0; k < HH/4; k++) {
        float4 wv = w4[k];
        float4 s4 = *(const float4*)&shr[k*4];
        acc += s4.x*wv.x + s4.y*wv.y + s4.z*wv.z + s4.w*wv.w;
    }
    recon[(size_t)(b0r+r)*TT*VV + (size_t)t*VV + v] = acc;
    sv[r*VV + v] = acc;
    si[r*VV + v] = v;
    __syncthreads();
    for (int s2 = 64; s2 > 0; s2 >>= 1) {
        if (v < s2) {
            float ov = sv[r*VV + v + s2]; int oi = si[r*VV + v + s2];
            if (ov > sv[r*VV + v] || (ov == sv[r*VV + v] && oi < si[r*VV + v])) {
                sv[r*VV + v] = ov; si[r*VV + v] = oi;
            }
        }
        __syncthreads();
    }
    const int tk = si[r*VV];
    const int b = b0r + r;
    const int h0c = v * 4;
    const float* pt = Ptab + (size_t)tk*GG;
    const float* p0 = part0 + (size_t)b*GG;
    float4 pi = *(const float4*)&pt[0*HH + h0c]; float4 qi = *(const float4*)&p0[0*HH + h0c];
    float4 pf = *(const float4*)&pt[1*HH + h0c]; float4 qf = *(const float4*)&p0[1*HH + h0c];
    float4 pg = *(const float4*)&pt[2*HH + h0c]; float4 qg = *(const float4*)&p0[2*HH + h0c];
    float4 po = *(const float4*)&pt[3*HH + h0c]; float4 qo = *(const float4*)&p0[3*HH + h0c];
    float4 c4 = *(const float4*)&dc0[(size_t)b*HH + h0c];
    float gi[4] = {pi.x+qi.x, pi.y+qi.y, pi.z+qi.z, pi.w+qi.w};
    float gf[4] = {pf.x+qf.x, pf.y+qf.y, pf.z+qf.z, pf.w+qf.w};
    float gg[4] = {pg.x+qg.x, pg.y+qg.y, pg.z+qg.z, pg.w+qg.w};
    float go[4] = {po.x+qo.x, po.y+qo.y, po.z+qo.z, po.w+qo.w};
    float cc[4] = {c4.x, c4.y, c4.z, c4.w};
    float co[4];
    #pragma unroll
    for (int j = 0; j < 4; j++) {
        float cn = sigf(gf[j])*cc[j] + sigf(gi[j])*tanhf(gg[j]);
        co[j] = cn;
        dh0T[(size_t)(h0c+j)*BB + b] = sigf(go[j])*tanhf(cn);
    }
    *(float4*)&dc0[(size_t)b*HH + h0c] = make_float4(co[0], co[1], co[2], co[3]);
}

// ---------------- cell0 at t=0 (token fixed = 1) ----------------
__global__ __launch_bounds__(128) void cell0_init_kernel(const float* __restrict__ Ptab,
                                                         const float* __restrict__ part0,
                                                         float* __restrict__ dc0,
                                                         float* __restrict__ dh0T) {
    const int b = blockIdx.x;
    const int h0c = threadIdx.x * 4;
    const float* pt = Ptab + (size_t)1*GG;
    const float* p0 = part0 + (size_t)b*GG;
    float4 pi = *(const float4*)&pt[0*HH + h0c]; float4 qi = *(const float4*)&p0[0*HH + h0c];
    float4 pf = *(const float4*)&pt[1*HH + h0c]; float4 qf = *(const float4*)&p0[1*HH + h0c];
    float4 pg = *(const float4*)&pt[2*HH + h0c]; float4 qg = *(const float4*)&p0[2*HH + h0c];
    float4 po = *(const float4*)&pt[3*HH + h0c]; float4 qo = *(const float4*)&p0[3*HH + h0c];
    float4 c4 = *(const float4*)&dc0[(size_t)b*HH + h0c];
    float gi[4] = {pi.x+qi.x, pi.y+qi.y, pi.z+qi.z, pi.w+qi.w};
    float gf[4] = {pf.x+qf.x, pf.y+qf.y, pf.z+qf.z, pf.w+qf.w};
    float gg[4] = {pg.x+qg.x, pg.y+qg.y, pg.z+qg.z, pg.w+qg.w};
    float go[4] = {po.x+qo.x, po.y+qo.y, po.z+qo.z, po.w+qo.w};
    float cc[4] = {c4.x, c4.y, c4.z, c4.w};
    float co[4];
    #pragma unroll
    for (int j = 0; j < 4; j++) {
        float cn = sigf(gf[j])*cc[j] + sigf(gi[j])*tanhf(gg[j]);
        co[j] = cn;
        dh0T[(size_t)(h0c+j)*BB + b] = sigf(go[j])*tanhf(cn);
    }
    *(float4*)&dc0[(size_t)b*HH + h0c] = make_float4(co[0], co[1], co[2], co[3]);
}

// ---------------- mu/logvar heads (transposed h inputs) ----------------
__global__ __launch_bounds__(256) void head_kernel(const float* __restrict__ hfT,
                                                   const float* __restrict__ hbT,
                                                   const float* __restrict__ Wmu,
                                                   const float* __restrict__ bmu,
                                                   const float* __restrict__ Wlv,
                                                   const float* __restrict__ blv,
                                                   float* __restrict__ out_mu,
                                                   float* __restrict__ out_lv,
                                                   float* __restrict__ zbuf) {
    int b = blockIdx.x;
    int tid = threadIdx.x;
    __shared__ float sh[2*HH];
    for (int i = tid; i < HH; i += 256) {
        sh[i]      = hfT[(size_t)i*LDH + b];
        sh[HH + i] = hbT[(size_t)i*LDH + b];
    }
    __syncthreads();
    const float* W;
    float acc;
    int l;
    if (tid < LL) { l = tid;      W = Wmu + (size_t)l*2*HH; acc = bmu[l]; }
    else          { l = tid - LL; W = Wlv + (size_t)l*2*HH; acc = blv[l]; }
    #pragma unroll 8
    for (int k = 0; k < 2*HH; k++) acc += sh[k]*W[k];
    if (tid < LL) { out_mu[b*LL + l] = acc; zbuf[b*LL + l] = acc; }
    else          { out_lv[b*LL + l] = acc; }
}

// ---------------- decoder init ----------------
__global__ __launch_bounds__(512) void dec_init_kernel(const float* __restrict__ z,
                                                       const float* __restrict__ W,
                                                       const float* __restrict__ bias,
                                                       float* __restrict__ h0T,
                                                       float* __restrict__ h1T,
                                                       float* __restrict__ h1n,
                                                       float* __restrict__ c0n,
                                                       float* __restrict__ c1T) {
    int b = blockIdx.x;
    int tid = threadIdx.x;   // = n
    __shared__ float sz[LL];
    if (tid < LL) sz[tid] = z[b*LL + tid];
    __syncthreads();
    float acc = bias[tid];
    const float* w = W + (size_t)tid*LL;
    #pragma unroll 8
    for (int k = 0; k < LL; k++) acc += sz[k]*w[k];
    h0T[(size_t)tid*BB + b] = acc;
    h1T[(size_t)tid*BB + b] = acc;
    h1n[(size_t)b*HH + tid] = acc;
    c0n[(size_t)b*HH + tid] = 0.0f;
    c1T[(size_t)tid*BB + b] = 0.0f;
}

// =================================== host launcher ====================================
extern "C" void kernel_launch(void* const* d_in, const int* in_sizes, int n_in,
                              void* d_out, int out_size) {
    const int*   x           = (const int*)  d_in[0];
    const float* emb         = (const float*)d_in[1];
    const float* enc_wih_l0  = (const float*)d_in[2];
    const float* enc_whh_l0  = (const float*)d_in[3];
    const float* enc_b_l0    = (const float*)d_in[4];
    const float* enc_wih_l1  = (const float*)d_in[5];
    const float* enc_whh_l1  = (const float*)d_in[6];
    const float* enc_b_l1    = (const float*)d_in[7];
    const float* fc_mu_w     = (const float*)d_in[8];
    const float* fc_mu_b     = (const float*)d_in[9];
    const float* fc_lv_w     = (const float*)d_in[10];
    const float* fc_lv_b     = (const float*)d_in[11];
    const float* dec_in_w    = (const float*)d_in[12];
    const float* dec_in_b    = (const float*)d_in[13];
    const float* dec_wih     = (const float*)d_in[14];
    const float* dec_whh     = (const float*)d_in[15];
    const float* dec_b       = (const float*)d_in[16];
    const float* dec_out_w   = (const float*)d_in[17];
    const float* dec_out_b   = (const float*)d_in[18];

    float* out       = (float*)d_out;
    float* out_recon = out;
    float* out_mu    = out + (size_t)BB*TT*VV;
    float* out_lv    = out_mu + (size_t)BB*LL;

    float *seqT, *seq1T, *y1fT, *y1bT, *preF, *preB;
    float *c0fT, *c0bT, *c1fT, *c1bT, *zeros, *zbuf;
    float *dh0T, *dh1T, *dh1n, *dc0, *dc1T, *part0, *part1, *ptab, *embT, *wt, *wt4;
    cudaGetSymbolAddress((void**)&seqT,  g_seqT);
    cudaGetSymbolAddress((void**)&seq1T, g_seq1T);
    cudaGetSymbolAddress((void**)&y1fT,  g_y1fT);
    cudaGetSymbolAddress((void**)&y1bT,  g_y1bT);
    cudaGetSymbolAddress((void**)&preF,  g_preF);
    cudaGetSymbolAddress((void**)&preB,  g_preB);
    cudaGetSymbolAddress((void**)&c0fT,  g_c0fT);
    cudaGetSymbolAddress((void**)&c0bT,  g_c0bT);
    cudaGetSymbolAddress((void**)&c1fT,  g_c1fT);
    cudaGetSymbolAddress((void**)&c1bT,  g_c1bT);
    cudaGetSymbolAddress((void**)&zeros, g_zeros);
    cudaGetSymbolAddress((void**)&zbuf,  g_z);
    cudaGetSymbolAddress((void**)&dh0T,  g_dh0T);
    cudaGetSymbolAddress((void**)&dh1T,  g_dh1T);
    cudaGetSymbolAddress((void**)&dh1n,  g_dh1n);
    cudaGetSymbolAddress((void**)&dc0,   g_dc0);
    cudaGetSymbolAddress((void**)&dc1T,  g_dc1T);
    cudaGetSymbolAddress((void**)&part0, g_part0);
    cudaGetSymbolAddress((void**)&part1, g_part1);
    cudaGetSymbolAddress((void**)&ptab,  g_ptab);
    cudaGetSymbolAddress((void**)&embT,  g_embT);
    cudaGetSymbolAddress((void**)&wt,    g_wt);
    cudaGetSymbolAddress((void**)&wt4,   g_wt4);

    const size_t M1 = 1024*1024;
    float* wtA0f = wt;            // enc_wih_l0 fwd  [512 x 2048]T
    float* wtA0b = wt + 1*M1;
    float* wtA1f = wt + 2*M1;     // enc_wih_l1 fwd  [1024 x 2048]T (2M)
    float* wtA1b = wt + 4*M1;
    float* wtPt  = wt + 6*M1;     // dec_wih0
    float* wtD0  = wt + 7*M1;     // dec_whh0
    float* wtD1  = wt + 8*M1;     // dec_whh1
    float* w4e0f = wt4;
    float* w4e0b = wt4 + 1*M1;
    float* w4e1f = wt4 + 2*M1;
    float* w4e1b = wt4 + 3*M1;
    float* w4ih1 = wt4 + 4*M1;
    float* w4hh0 = wt4 + 5*M1;
    float* w4hh1 = wt4 + 6*M1;

    const float* dWih0 = dec_wih;
    const float* dWih1 = dec_wih + (size_t)GG*HH;
    const float* dWhh0 = dec_whh;
    const float* dWhh1 = dec_whh + (size_t)GG*HH;
    const float* db0   = dec_b;
    const float* db1   = dec_b + GG;

    // ---- transforms (independent) ----
    embT_kernel<<<2048, 256>>>(x, emb, seqT);
    wt_kernel<<<512, 256>>>(emb, embT, VV, HH);
    wt_kernel<<<1024, 256>>>(enc_wih_l0,                 wtA0f, GG, HH);
    wt_kernel<<<1024, 256>>>(enc_wih_l0 + (size_t)GG*HH, wtA0b, GG, HH);
    wt_kernel<<<2048, 256>>>(enc_wih_l1,                    wtA1f, GG, 2*HH);
    wt_kernel<<<2048, 256>>>(enc_wih_l1 + (size_t)GG*2*HH,  wtA1b, GG, 2*HH);
    wt_kernel<<<1024, 256>>>(dWih0, wtPt, GG, HH);
    wt_kernel<<<1024, 256>>>(dWhh0, wtD0, GG, HH);
    wt_kernel<<<1024, 256>>>(dWhh1, wtD1, GG, HH);
    wt4_kernel<<<1024, 256>>>(enc_whh_l0,                 w4e0f);
    wt4_kernel<<<1024, 256>>>(enc_whh_l0 + (size_t)GG*HH, w4e0b);
    wt4_kernel<<<1024, 256>>>(enc_whh_l1,                 w4e1f);
    wt4_kernel<<<1024, 256>>>(enc_whh_l1 + (size_t)GG*HH, w4e1b);
    wt4_kernel<<<1024, 256>>>(dWih1, w4ih1);
    wt4_kernel<<<1024, 256>>>(dWhh0, w4hh0);
    wt4_kernel<<<1024, 256>>>(dWhh1, w4hh1);

    // ---- Ptab (decoder token table) ----
    sgemm_ca<<<dim3(GG/128, VV/128), 256>>>(embT, wtPt, db0, ptab, VV, GG, HH);

    // ---- encoder layer 0 ----
    dim3 preGrd(GG/128, LDH/128);
    sgemm_ca<<<preGrd, 256>>>(seqT, wtA0f, enc_b_l0,      preF, LDH, GG, HH);
    sgemm_ca<<<preGrd, 256>>>(seqT, wtA0b, enc_b_l0 + GG, preB, LDH, GG, HH);

    dim3 stepGrd(HH/32, BB/64, 2);   // (16,4,2)=128 blocks x 512 threads
    float* seq1Tb = seq1T + (size_t)HH*LDH;   // bwd rows
    for (int s = 0; s < TT; s++) {
        int tf = s, tb = TT-1-s;
        DirT df = { preF + (size_t)tf*BB*GG,
                    s ? seq1T + (size_t)(tf-1)*BB : zeros, s ? LDH : BB,
                    s ? c0fT : zeros, c0fT,
                    seq1T + (size_t)tf*BB, w4e0f };
        DirT db = { preB + (size_t)tb*BB*GG,
                    s ? seq1Tb + (size_t)(tb+1)*BB : zeros, s ? LDH : BB,
                    s ? c0bT : zeros, c0bT,
                    seq1Tb + (size_t)tb*BB, w4e0b };
        lstm_stepT<<<stepGrd, 512>>>(df, db);
    }

    // ---- encoder layer 1 (A = seq1T, K = 1024; no concat needed) ----
    sgemm_ca<<<preGrd, 256>>>(seq1T, wtA1f, enc_b_l1,      preF, LDH, GG, 2*HH);
    sgemm_ca<<<preGrd, 256>>>(seq1T, wtA1b, enc_b_l1 + GG, preB, LDH, GG, 2*HH);
    for (int s = 0; s < TT; s++) {
        int tf = s, tb = TT-1-s;
        DirT df = { preF + (size_t)tf*BB*GG,
                    s ? y1fT + (size_t)(tf-1)*BB : zeros, s ? LDH : BB,
                    s ? c1fT : zeros, c1fT,
                    y1fT + (size_t)tf*BB, w4e1f };
        DirT db = { preB + (size_t)tb*BB*GG,
                    s ? y1bT + (size_t)(tb+1)*BB : zeros, s ? LDH : BB,
                    s ? c1bT : zeros, c1bT,
                    y1bT + (size_t)tb*BB, w4e1b };
        lstm_stepT<<<stepGrd, 512>>>(df, db);
    }

    // ---- heads ----
    head_kernel<<<BB, 256>>>(y1fT + (size_t)(TT-1)*BB, y1bT,
                             fc_mu_w, fc_mu_b, fc_lv_w, fc_lv_b,
                             out_mu, out_lv, zbuf);

    // ---- decoder init ----
    dec_init_kernel<<<BB, 512>>>(zbuf, dec_in_w, dec_in_b, dh0T, dh1T, dh1n, dc0, dc1T);
    dim3 partGrd(GG/128, BB/128);
    sgemm_ca<<<partGrd, 256>>>(dh0T, wtD0, zeros, part0, BB, GG, HH);  // bias folded in Ptab
    sgemm_ca<<<partGrd, 256>>>(dh1T, wtD1, db1,   part1, BB, GG, HH);
    cell0_init_kernel<<<BB, 128>>>(ptab, part0, dc0, dh0T);

    // ---- autoregressive decode: 2 launches per step ----
    dim3 decGrd(HH/32, BB/64, 2);
    for (int t = 0; t < TT; t++) {
        dec_Y<<<decGrd, 512>>>(dh0T, w4ih1, part1, dc1T, dh1T, dh1n, w4hh0, zeros, part0);
        dec_Z<<<decGrd, 512>>>(dh1T, dh1n, dec_out_w, dec_out_b, w4hh1, db1, part1,
                               ptab, part0, dc0, dh0T, out_recon, t);
    }
}

// round 9
// speedup vs baseline: 1.4510x; 1.0370x over previous
#include <cuda_runtime.h>
#include <math.h>

// ---------------- problem constants ----------------
#define TT 128
#define BB 256
#define HH 512
#define GG 2048
#define VV 128
#define LL 128
#define LDH (TT*BB)

typedef unsigned long long u64t;

__device__ __forceinline__ u64t pack2(float x, float y) {
    u64t r; asm("mov.b64 %0, {%1, %2};" : "=l"(r) : "f"(x), "f"(y)); return r;
}
__device__ __forceinline__ void fma2(u64t& d, u64t a, u64t b) {
    asm("fma.rn.f32x2 %0, %1, %2, %0;" : "+l"(d) : "l"(a), "l"(b));
}
__device__ __forceinline__ void add2(u64t& d, u64t a) {
    asm("add.rn.f32x2 %0, %0, %1;" : "+l"(d) : "l"(a));
}
__device__ __forceinline__ float2 unpack2(u64t v) {
    float2 r; asm("mov.b64 {%0, %1}, %2;" : "=f"(r.x), "=f"(r.y) : "l"(v)); return r;
}
__device__ __forceinline__ unsigned smem_u32(const void* p) {
    return (unsigned)__cvta_generic_to_shared(p);
}
#define CP16(dst, src) asm volatile("cp.async.ca.shared.global [%0], [%1], 16;" :: "r"(dst), "l"((const void*)(src)) : "memory")
#define CP_COMMIT      asm volatile("cp.async.commit_group;" ::: "memory")
#define CP_WAIT1       asm volatile("cp.async.wait_group 1;" ::: "memory")
#define CP_WAIT0       asm volatile("cp.async.wait_group 0;" ::: "memory")

// fast transcendentals via MUFU (ex2 ~2^-22, rcp ~2^-23 rel err)
__device__ __forceinline__ float ex2f(float x) { float r; asm("ex2.approx.ftz.f32 %0, %1;" : "=f"(r) : "f"(x)); return r; }
__device__ __forceinline__ float rcpf(float x) { float r; asm("rcp.approx.ftz.f32 %0, %1;" : "=f"(r) : "f"(x)); return r; }
__device__ __forceinline__ float sigf(float v)  { return rcpf(1.0f + ex2f(-1.4426950408889634f*v)); }
__device__ __forceinline__ float tanhf_(float v){ return 2.0f*rcpf(1.0f + ex2f(-2.8853900817779268f*v)) - 1.0f; }

// ---------------- device scratch ----------------
__device__ __align__(16) float g_seqT [HH*LDH];
__device__ __align__(16) float g_seq1T[2*HH*LDH];
__device__ __align__(16) float g_y1fT [HH*LDH];
__device__ __align__(16) float g_y1bT [HH*LDH];
__device__ __align__(16) float g_preF [TT*BB*GG];
__device__ __align__(16) float g_preB [TT*BB*GG];
__device__ __align__(16) float g_c0fT [HH*BB];
__device__ __align__(16) float g_c0bT [HH*BB];
__device__ __align__(16) float g_c1fT [HH*BB];
__device__ __align__(16) float g_c1bT [HH*BB];
__device__ __align__(16) float g_zeros[HH*BB];
__device__ __align__(16) float g_z    [BB*LL];
__device__ __align__(16) float g_dh0T [HH*BB];
__device__ __align__(16) float g_dh1T [HH*BB];
__device__ __align__(16) float g_dh1n [BB*HH];
__device__ __align__(16) float g_dc0  [BB*HH];
__device__ __align__(16) float g_dc1T [HH*BB];
__device__ __align__(16) float g_part0 [BB*GG];
__device__ __align__(16) float g_part1a[BB*GG];
__device__ __align__(16) float g_part1b[BB*GG];
__device__ __align__(16) float g_ptab [VV*GG];
__device__ __align__(16) float g_embT [HH*VV];
__device__ __align__(16) float g_wt   [9*1024*1024];
__device__ __align__(16) float g_wt4  [7*1024*1024];

// ---------------- transforms ----------------
__global__ void wt_kernel(const float* __restrict__ in, float* __restrict__ out,
                          int N, int K) {
    int total = N*K;
    for (int i = blockIdx.x*blockDim.x + threadIdx.x; i < total; i += gridDim.x*blockDim.x) {
        int n = i % N; int k = i / N;
        out[i] = in[(size_t)n*K + k];
    }
}
__global__ void wt4_kernel(const float* __restrict__ in, float* __restrict__ out) {
    int total = HH*GG;
    for (int i = blockIdx.x*blockDim.x + threadIdx.x; i < total; i += gridDim.x*blockDim.x) {
        int g = i & 3; int n = (i >> 2) & 511; int k = i >> 11;
        out[i] = in[((size_t)(g*HH + n))*HH + k];
    }
}
__global__ void embT_kernel(const int* __restrict__ x, const float* __restrict__ emb,
                            float* __restrict__ seqT) {
    int total = HH*LDH;
    for (int i = blockIdx.x*blockDim.x + threadIdx.x; i < total; i += gridDim.x*blockDim.x) {
        int k = i / LDH; int m = i % LDH;
        int t = m / BB;  int b = m % BB;
        seqT[i] = emb[x[b*TT + t]*HH + k];
    }
}

// ================= sgemm_ca: C[M,N] = AT^T @ WT + bias =================
__global__ __launch_bounds__(256, 2) void sgemm_ca(const float* __restrict__ AT,
                                                   const float* __restrict__ WT,
                                                   const float* __restrict__ bias,
                                                   float* __restrict__ C,
                                                   int M, int N, int K) {
    __shared__ __align__(16) float S[2*4096];
    const int bm = blockIdx.y * 128;
    const int bn = blockIdx.x * 128;
    const int tid = threadIdx.x;
    const int tx = tid % 16;
    const int ty = tid / 16;
    const int NS = K / 16;

    const int ck  = tid >> 5;
    const int co  = (tid & 31) * 4;
    const float* asrc = AT + (size_t)ck*M + bm + co;
    const float* wsrc = WT + (size_t)ck*N + bn + co;
    unsigned sb = smem_u32(S);
    unsigned adst = sb + ((ck*128 + co) << 2);
    unsigned wdst = sb + ((2048 + ck*128 + co) << 2);

    #define PRE_ISSUE(s) { unsigned o_ = ((s)&1)*16384u; size_t ka_ = (size_t)(s)*16*M, kw_ = (size_t)(s)*16*N; \
        CP16(adst + o_, asrc + ka_); CP16(adst + o_ + 4096u, asrc + ka_ + 8*(size_t)M); \
        CP16(wdst + o_, wsrc + kw_); CP16(wdst + o_ + 4096u, wsrc + kw_ + 8*(size_t)N); CP_COMMIT; }

    u64t acc2[4][8];
    #pragma unroll
    for (int p = 0; p < 4; p++)
        #pragma unroll
        for (int j = 0; j < 8; j++) acc2[p][j] = 0ull;

    PRE_ISSUE(0);
    PRE_ISSUE(1);
    CP_WAIT1;
    __syncthreads();

    for (int s = 0; s < NS; s++) {
        const float* Bq = S + (s & 1)*4096;
        #pragma unroll
        for (int k = 0; k < 16; k++) {
            ulonglong2 A0 = *(const ulonglong2*)&Bq[k*128 + ty*8];
            ulonglong2 A1 = *(const ulonglong2*)&Bq[k*128 + ty*8 + 4];
            u64t apair[4] = {A0.x, A0.y, A1.x, A1.y};
            float w[8];
            *(float4*)&w[0] = *(const float4*)&Bq[2048 + k*128 + tx*8];
            *(float4*)&w[4] = *(const float4*)&Bq[2048 + k*128 + tx*8 + 4];
            #pragma unroll
            for (int j = 0; j < 8; j++) {
                u64t w2 = pack2(w[j], w[j]);
                #pragma unroll
                for (int p = 0; p < 4; p++) fma2(acc2[p][j], apair[p], w2);
            }
        }
        if (s == NS - 1) break;
        __syncthreads();
        if (s + 2 < NS) { PRE_ISSUE(s+2); CP_WAIT1; }
        else            { CP_WAIT0; }
        __syncthreads();
    }

    float bb[8];
    *(float4*)&bb[0] = *(const float4*)(bias + bn + tx*8);
    *(float4*)&bb[4] = *(const float4*)(bias + bn + tx*8 + 4);
    #pragma unroll
    for (int p = 0; p < 4; p++) {
        float2 v[8];
        #pragma unroll
        for (int j = 0; j < 8; j++) v[j] = unpack2(acc2[p][j]);
        #pragma unroll
        for (int sub = 0; sub < 2; sub++) {
            size_t row = (size_t)(bm + ty*8 + 2*p + sub)*N + bn + tx*8;
            float o[8];
            #pragma unroll
            for (int j = 0; j < 8; j++) o[j] = (sub ? v[j].y : v[j].x) + bb[j];
            *(float4*)&C[row]     = *(float4*)&o[0];
            *(float4*)&C[row + 4] = *(float4*)&o[4];
        }
    }
    #undef PRE_ISSUE
}

// ====== gate GEMM core: split-K (512 thr), cp.async, K-major, small I-footprint ========
#define GBUF 3072
#define GHALF (2*GBUF)
#define GSMEM (2*GHALF)     // 12288 floats = 48 KB

template<int NST>
__device__ __forceinline__ void gate_gemm_ca(const float* __restrict__ hT, int lda,
                                             const float* __restrict__ WT4,
                                             int bm, int bn, int kbeg,
                                             float* __restrict__ base,
                                             u64t acc2[4][4]) {
    const int lt = threadIdx.x & 255;
    const int tx = lt & 31;
    const int ty = lt >> 5;

    const float* hsrc = hT + (size_t)(kbeg + (lt >> 4))*lda + bm + (lt & 15)*4;
    const float* wsrc = WT4 + (size_t)(kbeg + (lt >> 5))*GG + (size_t)bn*4 + (lt & 31)*4;
    unsigned sb = smem_u32(base);
    unsigned hdst = sb + (((lt >> 4)*64 + (lt & 15)*4) << 2);
    unsigned wdst = sb + ((1024 + (lt >> 5)*128 + (lt & 31)*4) << 2);

    #define G_ISSUE(s) { unsigned o_ = ((s)&1)*(GBUF*4u); size_t kh_ = (size_t)(s)*16*lda, kw_ = (size_t)(s)*16*GG; \
        CP16(hdst + o_, hsrc + kh_); \
        CP16(wdst + o_, wsrc + kw_); CP16(wdst + o_ + 4096u, wsrc + kw_ + 8*(size_t)GG); CP_COMMIT; }

    G_ISSUE(0);
    G_ISSUE(1);
    CP_WAIT1;
    __syncthreads();

    // partial unroll: keeps mainloop body ~12 KB (I$-resident; grid<148 throttle avoided)
    #pragma unroll 2
    for (int s = 0; s < NST; s++) {
        const float* Bq = base + (s & 1)*GBUF;
        #pragma unroll
        for (int k = 0; k < 16; k++) {
            ulonglong2 A0 = *(const ulonglong2*)&Bq[k*64 + ty*8];
            ulonglong2 A1 = *(const ulonglong2*)&Bq[k*64 + ty*8 + 4];
            float4 wv = *(const float4*)&Bq[1024 + k*128 + tx*4];
            u64t wi  = pack2(wv.x, wv.x);
            u64t wf  = pack2(wv.y, wv.y);
            u64t wg2 = pack2(wv.z, wv.z);
            u64t wo  = pack2(wv.w, wv.w);
            fma2(acc2[0][0], A0.x, wi);  fma2(acc2[0][1], A0.y, wi);
            fma2(acc2[0][2], A1.x, wi);  fma2(acc2[0][3], A1.y, wi);
            fma2(acc2[1][0], A0.x, wf);  fma2(acc2[1][1], A0.y, wf);
            fma2(acc2[1][2], A1.x, wf);  fma2(acc2[1][3], A1.y, wf);
            fma2(acc2[2][0], A0.x, wg2); fma2(acc2[2][1], A0.y, wg2);
            fma2(acc2[2][2], A1.x, wg2); fma2(acc2[2][3], A1.y, wg2);
            fma2(acc2[3][0], A0.x, wo);  fma2(acc2[3][1], A0.y, wo);
            fma2(acc2[3][2], A1.x, wo);  fma2(acc2[3][3], A1.y, wo);
        }
        if (s == NST - 1) break;
        __syncthreads();
        if (s + 2 < NST) { G_ISSUE(s+2); CP_WAIT1; }
        else             { CP_WAIT0; }
        __syncthreads();
    }
    #undef G_ISSUE
}

__device__ __forceinline__ void ksplit_merge(float* __restrict__ smemAll,
                                             u64t acc2[4][4], int half) {
    u64t* red = reinterpret_cast<u64t*>(smemAll);
    const int lt = threadIdx.x & 255;
    __syncthreads();
    if (half == 1) {
        #pragma unroll
        for (int g = 0; g < 4; g++)
            #pragma unroll
            for (int p = 0; p < 4; p++)
                red[lt*16 + g*4 + p] = acc2[g][p];
    }
    __syncthreads();
    if (half == 0) {
        #pragma unroll
        for (int g = 0; g < 4; g++)
            #pragma unroll
            for (int p = 0; p < 4; p++)
                add2(acc2[g][p], red[lt*16 + g*4 + p]);
    }
}

// Epilogue; pre2 optional second partial buffer (summed with pre).
__device__ __forceinline__ void lstm_epiT(u64t acc2[4][4],
                                          const float* __restrict__ pre,
                                          const float* __restrict__ pre2,
                                          const float* __restrict__ cinT,
                                          float* __restrict__ coutT,
                                          float* __restrict__ houtT, int ldh,
                                          float* __restrict__ houtN,
                                          int bm, int bn) {
    const int lt = threadIdx.x & 255;
    const int tx = lt & 31;
    const int ty = lt >> 5;
    const int n  = bn + tx;
    const int b0 = bm + ty*8;
    float cv[8], hv[8], co[8];
    *(float4*)&cv[0] = *(const float4*)&cinT[(size_t)n*BB + b0];
    *(float4*)&cv[4] = *(const float4*)&cinT[(size_t)n*BB + b0 + 4];
    #pragma unroll
    for (int p = 0; p < 4; p++) {
        float2 vi = unpack2(acc2[0][p]);
        float2 vf = unpack2(acc2[1][p]);
        float2 vg = unpack2(acc2[2][p]);
        float2 vo = unpack2(acc2[3][p]);
        #pragma unroll
        for (int sub = 0; sub < 2; sub++) {
            int idx = 2*p + sub;
            int b = b0 + idx;
            const float* pb = pre + (size_t)b*GG;
            float gi = pb[0*HH + n] + (sub ? vi.y : vi.x);
            float gf = pb[1*HH + n] + (sub ? vf.y : vf.x);
            float gg = pb[2*HH + n] + (sub ? vg.y : vg.x);
            float go = pb[3*HH + n] + (sub ? vo.y : vo.x);
            if (pre2) {
                const float* pc = pre2 + (size_t)b*GG;
                gi += pc[0*HH + n]; gf += pc[1*HH + n];
                gg += pc[2*HH + n]; go += pc[3*HH + n];
            }
            float cn = sigf(gf)*cv[idx] + sigf(gi)*tanhf_(gg);
            co[idx] = cn;
            hv[idx] = sigf(go)*tanhf_(cn);
        }
    }
    *(float4*)&coutT[(size_t)n*BB + b0]     = *(float4*)&co[0];
    *(float4*)&coutT[(size_t)n*BB + b0 + 4] = *(float4*)&co[4];
    *(float4*)&houtT[(size_t)n*ldh + b0]     = *(float4*)&hv[0];
    *(float4*)&houtT[(size_t)n*ldh + b0 + 4] = *(float4*)&hv[4];
    if (houtN) {
        #pragma unroll
        for (int i = 0; i < 8; i++) houtN[(size_t)(b0+i)*HH + n] = hv[i];
    }
}

__device__ __forceinline__ void part_store(u64t acc2[4][4],
                                           const float* __restrict__ bias,
                                           float* __restrict__ outp,
                                           int bm, int bn) {
    const int lt = threadIdx.x & 255;
    const int tx = lt & 31;
    const int ty = lt >> 5;
    const int n = bn + tx;
    #pragma unroll
    for (int g = 0; g < 4; g++) {
        float bv = bias[g*HH + n];
        #pragma unroll
        for (int p = 0; p < 4; p++) {
            float2 v = unpack2(acc2[g][p]);
            int b0 = bm + ty*8 + 2*p;
            outp[(size_t)(b0+0)*GG + g*HH + n] = v.x + bv;
            outp[(size_t)(b0+1)*GG + g*HH + n] = v.y + bv;
        }
    }
}

#define ZERO_ACC(a) { _Pragma("unroll") for (int g_=0; g_<4; g_++) { \
    _Pragma("unroll") for (int p_=0; p_<4; p_++) (a)[g_][p_] = 0ull; } }

// ---------------- encoder recurrent step ----------------
struct DirT {
    const float* pre;
    const float* hinT; int lda;
    const float* cinT;
    float* coutT;
    float* houtT;
    const float* WT4;
};

__global__ __launch_bounds__(512, 1) void lstm_stepT(DirT A0, DirT A1) {
    __shared__ __align__(16) float S[GSMEM];
    DirT d = blockIdx.z ? A1 : A0;
    const int half = threadIdx.x >> 8;
    float* base = S + half*GHALF;
    int bm = blockIdx.y * 64;
    int bn = blockIdx.x * 32;
    u64t acc2[4][4];
    ZERO_ACC(acc2);
    gate_gemm_ca<16>(d.hinT, d.lda, d.WT4, bm, bn, half*256, base, acc2);
    ksplit_merge(S, acc2, half);
    if (half == 0)
        lstm_epiT(acc2, d.pre, nullptr, d.cinT, d.coutT, d.houtT, LDH, nullptr, bm, bn);
}

// ---------------- decoder phase Y: cell1 (z=0) || part0' (z=1) ----------------
__global__ __launch_bounds__(512, 1) void dec_Y(const float* __restrict__ dh0T,
                                                const float* __restrict__ w4ih1,
                                                const float* __restrict__ part1a,
                                                const float* __restrict__ part1b,
                                                float* __restrict__ dc1T,
                                                float* __restrict__ dh1T,
                                                float* __restrict__ dh1n,
                                                const float* __restrict__ w4hh0,
                                                const float* __restrict__ zerob,
                                                float* __restrict__ part0) {
    __shared__ __align__(16) float S[GSMEM];
    const int half = threadIdx.x >> 8;
    float* base = S + half*GHALF;
    int bm = blockIdx.y * 64;
    int bn = blockIdx.x * 32;
    u64t acc2[4][4];
    ZERO_ACC(acc2);
    if (blockIdx.z == 0) {
        gate_gemm_ca<16>(dh0T, BB, w4ih1, bm, bn, half*256, base, acc2);
        ksplit_merge(S, acc2, half);
        if (half == 0) lstm_epiT(acc2, part1a, part1b, dc1T, dc1T, dh1T, BB, dh1n, bm, bn);
    } else {
        gate_gemm_ca<16>(dh0T, BB, w4hh0, bm, bn, half*256, base, acc2);
        ksplit_merge(S, acc2, half);
        if (half == 0) part_store(acc2, zerob, part0, bm, bn);
    }
}

// ---- phase Z: logits+argmax+cell0 (z=0) || part1a (z=1, K[0:256]) || part1b (z=2) -----
__global__ __launch_bounds__(512, 1) void dec_Z(const float* __restrict__ dh1T,
                                                const float* __restrict__ dh1n,
                                                const float* __restrict__ Wout,
                                                const float* __restrict__ bout,
                                                const float* __restrict__ w4hh1,
                                                const float* __restrict__ b1,
                                                const float* __restrict__ zerob,
                                                float* __restrict__ part1a,
                                                float* __restrict__ part1b,
                                                const float* __restrict__ Ptab,
                                                const float* __restrict__ part0,
                                                float* __restrict__ dc0,
                                                float* __restrict__ dh0T,
                                                float* __restrict__ recon,
                                                int t) {
    __shared__ __align__(16) float S[GSMEM];
    if (blockIdx.z >= 1) {
        const int half = threadIdx.x >> 8;
        float* base = S + half*GHALF;
        int bm = blockIdx.y * 64;
        int bn = blockIdx.x * 32;
        int kb = (blockIdx.z - 1) * 256 + half*128;
        u64t acc2[4][4];
        ZERO_ACC(acc2);
        gate_gemm_ca<8>(dh1T, BB, w4hh1, bm, bn, kb, base, acc2);
        ksplit_merge(S, acc2, half);
        if (half == 0) {
            if (blockIdx.z == 1) part_store(acc2, b1,    part1a, bm, bn);
            else                 part_store(acc2, zerob, part1b, bm, bn);
        }
        return;
    }
    const int tid = threadIdx.x;
    const int bid = blockIdx.y*16 + blockIdx.x;
    const int b0r = bid * 4;
    float* sh = S;
    float* sv = S + 4*HH;
    int*   si = (int*)(S + 4*HH + 4*VV);
    ((float4*)sh)[tid] = ((const float4*)(dh1n + (size_t)b0r*HH))[tid];
    __syncthreads();
    const int v = tid & 127;
    const int r = tid >> 7;
    const float4* w4 = (const float4*)(Wout + (size_t)v*HH);
    const float* shr = sh + r*HH;
    float acc = bout[v];
    #pragma unroll 8
    for (int k = 0; k < HH/4; k++) {
        float4 wv = w4[k];
        float4 s4 = *(const float4*)&shr[k*4];
        acc += s4.x*wv.x + s4.y*wv.y + s4.z*wv.z + s4.w*wv.w;
    }
    recon[(size_t)(b0r+r)*TT*VV + (size_t)t*VV + v] = acc;
    sv[r*VV + v] = acc;
    si[r*VV + v] = v;
    __syncthreads();
    for (int s2 = 64; s2 > 0; s2 >>= 1) {
        if (v < s2) {
            float ov = sv[r*VV + v + s2]; int oi = si[r*VV + v + s2];
            if (ov > sv[r*VV + v] || (ov == sv[r*VV + v] && oi < si[r*VV + v])) {
                sv[r*VV + v] = ov; si[r*VV + v] = oi;
            }
        }
        __syncthreads();
    }
    const int tk = si[r*VV];
    const int b = b0r + r;
    const int h0c = v * 4;
    const float* pt = Ptab + (size_t)tk*GG;
    const float* p0 = part0 + (size_t)b*GG;
    float4 pi = *(const float4*)&pt[0*HH + h0c]; float4 qi = *(const float4*)&p0[0*HH + h0c];
    float4 pf = *(const float4*)&pt[1*HH + h0c]; float4 qf = *(const float4*)&p0[1*HH + h0c];
    float4 pg = *(const float4*)&pt[2*HH + h0c]; float4 qg = *(const float4*)&p0[2*HH + h0c];
    float4 po = *(const float4*)&pt[3*HH + h0c]; float4 qo = *(const float4*)&p0[3*HH + h0c];
    float4 c4 = *(const float4*)&dc0[(size_t)b*HH + h0c];
    float gi[4] = {pi.x+qi.x, pi.y+qi.y, pi.z+qi.z, pi.w+qi.w};
    float gf[4] = {pf.x+qf.x, pf.y+qf.y, pf.z+qf.z, pf.w+qf.w};
    float gg[4] = {pg.x+qg.x, pg.y+qg.y, pg.z+qg.z, pg.w+qg.w};
    float go[4] = {po.x+qo.x, po.y+qo.y, po.z+qo.z, po.w+qo.w};
    float cc[4] = {c4.x, c4.y, c4.z, c4.w};
    float co[4];
    #pragma unroll
    for (int j = 0; j < 4; j++) {
        float cn = sigf(gf[j])*cc[j] + sigf(gi[j])*tanhf_(gg[j]);
        co[j] = cn;
        dh0T[(size_t)(h0c+j)*BB + b] = sigf(go[j])*tanhf_(cn);
    }
    *(float4*)&dc0[(size_t)b*HH + h0c] = make_float4(co[0], co[1], co[2], co[3]);
}

// ---------------- cell0 at t=0 ----------------
__global__ __launch_bounds__(128) void cell0_init_kernel(const float* __restrict__ Ptab,
                                                         const float* __restrict__ part0,
                                                         float* __restrict__ dc0,
                                                         float* __restrict__ dh0T) {
    const int b = blockIdx.x;
    const int h0c = threadIdx.x * 4;
    const float* pt = Ptab + (size_t)1*GG;
    const float* p0 = part0 + (size_t)b*GG;
    float4 pi = *(const float4*)&pt[0*HH + h0c]; float4 qi = *(const float4*)&p0[0*HH + h0c];
    float4 pf = *(const float4*)&pt[1*HH + h0c]; float4 qf = *(const float4*)&p0[1*HH + h0c];
    float4 pg = *(const float4*)&pt[2*HH + h0c]; float4 qg = *(const float4*)&p0[2*HH + h0c];
    float4 po = *(const float4*)&pt[3*HH + h0c]; float4 qo = *(const float4*)&p0[3*HH + h0c];
    float4 c4 = *(const float4*)&dc0[(size_t)b*HH + h0c];
    float gi[4] = {pi.x+qi.x, pi.y+qi.y, pi.z+qi.z, pi.w+qi.w};
    float gf[4] = {pf.x+qf.x, pf.y+qf.y, pf.z+qf.z, pf.w+qf.w};
    float gg[4] = {pg.x+qg.x, pg.y+qg.y, pg.z+qg.z, pg.w+qg.w};
    float go[4] = {po.x+qo.x, po.y+qo.y, po.z+qo.z, po.w+qo.w};
    float cc[4] = {c4.x, c4.y, c4.z, c4.w};
    float co[4];
    #pragma unroll
    for (int j = 0; j < 4; j++) {
        float cn = sigf(gf[j])*cc[j] + sigf(gi[j])*tanhf_(gg[j]);
        co[j] = cn;
        dh0T[(size_t)(h0c+j)*BB + b] = sigf(go[j])*tanhf_(cn);
    }
    *(float4*)&dc0[(size_t)b*HH + h0c] = make_float4(co[0], co[1], co[2], co[3]);
}

// ---------------- mu/logvar heads ----------------
__global__ __launch_bounds__(256) void head_kernel(const float* __restrict__ hfT,
                                                   const float* __restrict__ hbT,
                                                   const float* __restrict__ Wmu,
                                                   const float* __restrict__ bmu,
                                                   const float* __restrict__ Wlv,
                                                   const float* __restrict__ blv,
                                                   float* __restrict__ out_mu,
                                                   float* __restrict__ out_lv,
                                                   float* __restrict__ zbuf) {
    int b = blockIdx.x;
    int tid = threadIdx.x;
    __shared__ float sh[2*HH];
    for (int i = tid; i < HH; i += 256) {
        sh[i]      = hfT[(size_t)i*LDH + b];
        sh[HH + i] = hbT[(size_t)i*LDH + b];
    }
    __syncthreads();
    const float* W;
    float acc;
    int l;
    if (tid < LL) { l = tid;      W = Wmu + (size_t)l*2*HH; acc = bmu[l]; }
    else          { l = tid - LL; W = Wlv + (size_t)l*2*HH; acc = blv[l]; }
    #pragma unroll 8
    for (int k = 0; k < 2*HH; k++) acc += sh[k]*W[k];
    if (tid < LL) { out_mu[b*LL + l] = acc; zbuf[b*LL + l] = acc; }
    else          { out_lv[b*LL + l] = acc; }
}

// ---------------- decoder init ----------------
__global__ __launch_bounds__(512) void dec_init_kernel(const float* __restrict__ z,
                                                       const float* __restrict__ W,
                                                       const float* __restrict__ bias,
                                                       float* __restrict__ h0T,
                                                       float* __restrict__ h1T,
                                                       float* __restrict__ h1n,
                                                       float* __restrict__ c0n,
                                                       float* __restrict__ c1T) {
    int b = blockIdx.x;
    int tid = threadIdx.x;
    __shared__ float sz[LL];
    if (tid < LL) sz[tid] = z[b*LL + tid];
    __syncthreads();
    float acc = bias[tid];
    const float* w = W + (size_t)tid*LL;
    #pragma unroll 8
    for (int k = 0; k < LL; k++) acc += sz[k]*w[k];
    h0T[(size_t)tid*BB + b] = acc;
    h1T[(size_t)tid*BB + b] = acc;
    h1n[(size_t)b*HH + tid] = acc;
    c0n[(size_t)b*HH + tid] = 0.0f;
    c1T[(size_t)tid*BB + b] = 0.0f;
}

// =================================== host launcher ====================================
extern "C" void kernel_launch(void* const* d_in, const int* in_sizes, int n_in,
                              void* d_out, int out_size) {
    const int*   x           = (const int*)  d_in[0];
    const float* emb         = (const float*)d_in[1];
    const float* enc_wih_l0  = (const float*)d_in[2];
    const float* enc_whh_l0  = (const float*)d_in[3];
    const float* enc_b_l0    = (const float*)d_in[4];
    const float* enc_wih_l1  = (const float*)d_in[5];
    const float* enc_whh_l1  = (const float*)d_in[6];
    const float* enc_b_l1    = (const float*)d_in[7];
    const float* fc_mu_w     = (const float*)d_in[8];
    const float* fc_mu_b     = (const float*)d_in[9];
    const float* fc_lv_w     = (const float*)d_in[10];
    const float* fc_lv_b     = (const float*)d_in[11];
    const float* dec_in_w    = (const float*)d_in[12];
    const float* dec_in_b    = (const float*)d_in[13];
    const float* dec_wih     = (const float*)d_in[14];
    const float* dec_whh     = (const float*)d_in[15];
    const float* dec_b       = (const float*)d_in[16];
    const float* dec_out_w   = (const float*)d_in[17];
    const float* dec_out_b   = (const float*)d_in[18];

    float* out       = (float*)d_out;
    float* out_recon = out;
    float* out_mu    = out + (size_t)BB*TT*VV;
    float* out_lv    = out_mu + (size_t)BB*LL;

    float *seqT, *seq1T, *y1fT, *y1bT, *preF, *preB;
    float *c0fT, *c0bT, *c1fT, *c1bT, *zeros, *zbuf;
    float *dh0T, *dh1T, *dh1n, *dc0, *dc1T, *part0, *part1a, *part1b, *ptab, *embT, *wt, *wt4;
    cudaGetSymbolAddress((void**)&seqT,  g_seqT);
    cudaGetSymbolAddress((void**)&seq1T, g_seq1T);
    cudaGetSymbolAddress((void**)&y1fT,  g_y1fT);
    cudaGetSymbolAddress((void**)&y1bT,  g_y1bT);
    cudaGetSymbolAddress((void**)&preF,  g_preF);
    cudaGetSymbolAddress((void**)&preB,  g_preB);
    cudaGetSymbolAddress((void**)&c0fT,  g_c0fT);
    cudaGetSymbolAddress((void**)&c0bT,  g_c0bT);
    cudaGetSymbolAddress((void**)&c1fT,  g_c1fT);
    cudaGetSymbolAddress((void**)&c1bT,  g_c1bT);
    cudaGetSymbolAddress((void**)&zeros, g_zeros);
    cudaGetSymbolAddress((void**)&zbuf,  g_z);
    cudaGetSymbolAddress((void**)&dh0T,  g_dh0T);
    cudaGetSymbolAddress((void**)&dh1T,  g_dh1T);
    cudaGetSymbolAddress((void**)&dh1n,  g_dh1n);
    cudaGetSymbolAddress((void**)&dc0,   g_dc0);
    cudaGetSymbolAddress((void**)&dc1T,  g_dc1T);
    cudaGetSymbolAddress((void**)&part0, g_part0);
    cudaGetSymbolAddress((void**)&part1a,g_part1a);
    cudaGetSymbolAddress((void**)&part1b,g_part1b);
    cudaGetSymbolAddress((void**)&ptab,  g_ptab);
    cudaGetSymbolAddress((void**)&embT,  g_embT);
    cudaGetSymbolAddress((void**)&wt,    g_wt);
    cudaGetSymbolAddress((void**)&wt4,   g_wt4);

    const size_t M1 = 1024*1024;
    float* wtA0f = wt;
    float* wtA0b = wt + 1*M1;
    float* wtA1f = wt + 2*M1;
    float* wtA1b = wt + 4*M1;
    float* wtPt  = wt + 6*M1;
    float* wtD0  = wt + 7*M1;
    float* wtD1  = wt + 8*M1;
    float* w4e0f = wt4;
    float* w4e0b = wt4 + 1*M1;
    float* w4e1f = wt4 + 2*M1;
    float* w4e1b = wt4 + 3*M1;
    float* w4ih1 = wt4 + 4*M1;
    float* w4hh0 = wt4 + 5*M1;
    float* w4hh1 = wt4 + 6*M1;

    const float* dWih0 = dec_wih;
    const float* dWih1 = dec_wih + (size_t)GG*HH;
    const float* dWhh0 = dec_whh;
    const float* dWhh1 = dec_whh + (size_t)GG*HH;
    const float* db0   = dec_b;
    const float* db1   = dec_b + GG;

    // ---- transforms ----
    embT_kernel<<<2048, 256>>>(x, emb, seqT);
    wt_kernel<<<512, 256>>>(emb, embT, VV, HH);
    wt_kernel<<<1024, 256>>>(enc_wih_l0,                 wtA0f, GG, HH);
    wt_kernel<<<1024, 256>>>(enc_wih_l0 + (size_t)GG*HH, wtA0b, GG, HH);
    wt_kernel<<<2048, 256>>>(enc_wih_l1,                    wtA1f, GG, 2*HH);
    wt_kernel<<<2048, 256>>>(enc_wih_l1 + (size_t)GG*2*HH,  wtA1b, GG, 2*HH);
    wt_kernel<<<1024, 256>>>(dWih0, wtPt, GG, HH);
    wt_kernel<<<1024, 256>>>(dWhh0, wtD0, GG, HH);
    wt_kernel<<<1024, 256>>>(dWhh1, wtD1, GG, HH);
    wt4_kernel<<<1024, 256>>>(enc_whh_l0,                 w4e0f);
    wt4_kernel<<<1024, 256>>>(enc_whh_l0 + (size_t)GG*HH, w4e0b);
    wt4_kernel<<<1024, 256>>>(enc_whh_l1,                 w4e1f);
    wt4_kernel<<<1024, 256>>>(enc_whh_l1 + (size_t)GG*HH, w4e1b);
    wt4_kernel<<<1024, 256>>>(dWih1, w4ih1);
    wt4_kernel<<<1024, 256>>>(dWhh0, w4hh0);
    wt4_kernel<<<1024, 256>>>(dWhh1, w4hh1);

    // ---- Ptab ----
    sgemm_ca<<<dim3(GG/128, VV/128), 256>>>(embT, wtPt, db0, ptab, VV, GG, HH);

    // ---- encoder layer 0 ----
    dim3 preGrd(GG/128, LDH/128);
    sgemm_ca<<<preGrd, 256>>>(seqT, wtA0f, enc_b_l0,      preF, LDH, GG, HH);
    sgemm_ca<<<preGrd, 256>>>(seqT, wtA0b, enc_b_l0 + GG, preB, LDH, GG, HH);

    dim3 stepGrd(HH/32, BB/64, 2);
    float* seq1Tb = seq1T + (size_t)HH*LDH;
    for (int s = 0; s < TT; s++) {
        int tf = s, tb = TT-1-s;
        DirT df = { preF + (size_t)tf*BB*GG,
                    s ? seq1T + (size_t)(tf-1)*BB : zeros, s ? LDH : BB,
                    s ? c0fT : zeros, c0fT,
                    seq1T + (size_t)tf*BB, w4e0f };
        DirT db = { preB + (size_t)tb*BB*GG,
                    s ? seq1Tb + (size_t)(tb+1)*BB : zeros, s ? LDH : BB,
                    s ? c0bT : zeros, c0bT,
                    seq1Tb + (size_t)tb*BB, w4e0b };
        lstm_stepT<<<stepGrd, 512>>>(df, db);
    }

    // ---- encoder layer 1 ----
    sgemm_ca<<<preGrd, 256>>>(seq1T, wtA1f, enc_b_l1,      preF, LDH, GG, 2*HH);
    sgemm_ca<<<preGrd, 256>>>(seq1T, wtA1b, enc_b_l1 + GG, preB, LDH, GG, 2*HH);
    for (int s = 0; s < TT; s++) {
        int tf = s, tb = TT-1-s;
        DirT df = { preF + (size_t)tf*BB*GG,
                    s ? y1fT + (size_t)(tf-1)*BB : zeros, s ? LDH : BB,
                    s ? c1fT : zeros, c1fT,
                    y1fT + (size_t)tf*BB, w4e1f };
        DirT db = { preB + (size_t)tb*BB*GG,
                    s ? y1bT + (size_t)(tb+1)*BB : zeros, s ? LDH : BB,
                    s ? c1bT : zeros, c1bT,
                    y1bT + (size_t)tb*BB, w4e1b };
        lstm_stepT<<<stepGrd, 512>>>(df, db);
    }

    // ---- heads ----
    head_kernel<<<BB, 256>>>(y1fT + (size_t)(TT-1)*BB, y1bT,
                             fc_mu_w, fc_mu_b, fc_lv_w, fc_lv_b,
                             out_mu, out_lv, zbuf);

    // ---- decoder init ----
    dec_init_kernel<<<BB, 512>>>(zbuf, dec_in_w, dec_in_b, dh0T, dh1T, dh1n, dc0, dc1T);
    dim3 partGrd(GG/128, BB/128);
    sgemm_ca<<<partGrd, 256>>>(dh0T, wtD0, zeros, part0,  BB, GG, HH);
    sgemm_ca<<<partGrd, 256>>>(dh1T, wtD1, db1,   part1a, BB, GG, HH);
    cudaMemsetAsync(part1b, 0, (size_t)BB*GG*sizeof(float));
    cell0_init_kernel<<<BB, 128>>>(ptab, part0, dc0, dh0T);

    // ---- autoregressive decode ----
    dim3 yGrd(HH/32, BB/64, 2);
    dim3 zGrd(HH/32, BB/64, 3);
    for (int t = 0; t < TT; t++) {
        dec_Y<<<yGrd, 512>>>(dh0T, w4ih1, part1a, part1b, dc1T, dh1T, dh1n,
                             w4hh0, zeros, part0);
        dec_Z<<<zGrd, 512>>>(dh1T, dh1n, dec_out_w, dec_out_b, w4hh1, db1, zeros,
                             part1a, part1b, ptab, part0, dc0, dh0T, out_recon, t);
    }
}